// round 11
// baseline (speedup 1.0000x reference)
#include <cuda_runtime.h>
#include <cstdint>

#define D_MODEL 1024
#define N_HEADS 16
#define DK      64
#define SEQ     2048
#define BATCH   2
#define ROWS    (BATCH * SEQ)          /* 4096 */
#define BH      (BATCH * N_HEADS)      /* 32 */
#define LN_EPS  1e-5f

#define SY ((long long)ROWS * D_MODEL)                         /* 4194304  */
#define SA ((long long)BH * SEQ * SEQ)                         /* 134217728 */

// ---------------- scratch (static device globals: no runtime alloc) --------
__device__ float g_q  [ROWS * D_MODEL];
__device__ float g_k  [ROWS * D_MODEL];
__device__ float g_v  [ROWS * D_MODEL];
__device__ float g_ctx[ROWS * D_MODEL];
__device__ float g_o  [ROWS * D_MODEL];
__device__ float g_xr [ROWS * D_MODEL];               // tf32-rounded x
__device__ float g_wr [4 * D_MODEL * D_MODEL];        // tf32-rounded weights
__device__ float g_sc [(size_t)BH * SEQ * SEQ];       // attn fallback buffer
__device__ float g_l  [BH * SEQ];                     // row sums of exp

// ---------------- helpers --------------------------------------------------
__device__ __forceinline__ float tf32r(float f) {
    uint32_t u;
    asm("cvt.rna.tf32.f32 %0, %1;" : "=r"(u) : "f"(f));
    return __uint_as_float(u);
}
// operands pre-rounded: raw bits are exact tf32
__device__ __forceinline__ uint32_t bits(float f) { return __float_as_uint(f); }

__device__ __forceinline__ void cp16(void* smem, const void* g) {
    uint32_t a = (uint32_t)__cvta_generic_to_shared(smem);
    asm volatile("cp.async.cg.shared.global [%0], [%1], 16;" :: "r"(a), "l"(g));
}
#define CP_COMMIT()  asm volatile("cp.async.commit_group;")
#define CP_WAIT(n)   asm volatile("cp.async.wait_group %0;" :: "n"(n))

__device__ __forceinline__ void mma_tf32(float c[4],
    uint32_t a0, uint32_t a1, uint32_t a2, uint32_t a3,
    uint32_t b0, uint32_t b1)
{
    asm volatile(
        "mma.sync.aligned.m16n8k8.row.col.f32.tf32.tf32.f32 "
        "{%0,%1,%2,%3}, {%4,%5,%6,%7}, {%8,%9}, {%0,%1,%2,%3};"
        : "+f"(c[0]), "+f"(c[1]), "+f"(c[2]), "+f"(c[3])
        : "r"(a0), "r"(a1), "r"(a2), "r"(a3), "r"(b0), "r"(b1));
}

__device__ __forceinline__ float warpReduceSum(float v) {
#pragma unroll
    for (int o = 16; o > 0; o >>= 1) v += __shfl_xor_sync(0xffffffffu, v, o);
    return v;
}
__device__ __forceinline__ float blockReduceSum(float v) {
    __shared__ float sh[8];
    __shared__ float res;
    int lane = threadIdx.x & 31, w = threadIdx.x >> 5;
    v = warpReduceSum(v);
    if (lane == 0) sh[w] = v;
    __syncthreads();
    if (w == 0) {
        float t = (lane < 8) ? sh[lane] : 0.0f;
        t = warpReduceSum(t);
        if (lane == 0) res = t;
    }
    __syncthreads();
    float r = res;
    __syncthreads();
    return r;
}

// ---------------- merged tf32-RNA rounding (x + 4 weights) -----------------
#define NX4 ((int)(SY / 4))
#define NW4 (D_MODEL * D_MODEL / 4)
__global__ void __launch_bounds__(256)
round_all(const float4* __restrict__ x,
          const float4* __restrict__ Wq, const float4* __restrict__ Wk,
          const float4* __restrict__ Wv, const float4* __restrict__ Wo,
          float4* __restrict__ xr, float4* __restrict__ wr)
{
    int n4 = NX4 + 4 * NW4;
    for (int i = blockIdx.x * blockDim.x + threadIdx.x; i < n4;
         i += gridDim.x * blockDim.x) {
        const float4* src;
        float4* dst;
        if (i < NX4) { src = x + i; dst = xr + i; }
        else {
            int j = i - NX4;
            int ws = j / NW4, off = j - ws * NW4;
            src = (ws == 0 ? Wq : ws == 1 ? Wk : ws == 2 ? Wv : Wo) + off;
            dst = wr + (long long)ws * NW4 + off;
        }
        float4 v = *src;
        v.x = tf32r(v.x); v.y = tf32r(v.y); v.z = tf32r(v.z); v.w = tf32r(v.w);
        *dst = v;
    }
}

// ---------------- tf32 GEMM NT core ---------------------------------------
// EXPSTATS: per-row sums of exp(alpha*acc) -> atomics to lbuf; no C stores.
// RNDOUT: round outputs to tf32 (raw-bit consumption downstream).
template<int BN, bool EXPSTATS, bool RNDOUT>
__device__ __forceinline__ void gemm_nt_core(
    const float* __restrict__ A, int lda,
    const float* __restrict__ B, int ldb,
    float* __restrict__ C, int ldc, int K, float alpha,
    float* __restrict__ lbuf)
{
    constexpr int BM  = 128;
    constexpr int BK  = 16;
    constexpr int STR = 20;
    constexpr int TNW = BN / 4;
    constexpr int TNT = BN / 32;

    __shared__ float As[2][BM * STR];
    __shared__ float Bs[2][BN * STR];

    int t    = threadIdx.x;
    int w    = t >> 5, lane = t & 31;
    int wm   = w >> 2, wn = w & 3;
    int g    = lane >> 2, tg = lane & 3;

    const float* Ag = A + (long long)(blockIdx.y * BM) * lda;
    const float* Bg = B + (long long)(blockIdx.x * BN) * ldb;

    int lr = t >> 2;
    int lc = (t & 3) * 4;

    float acc[4][TNT][4];
#pragma unroll
    for (int i = 0; i < 4; i++)
#pragma unroll
        for (int j = 0; j < TNT; j++)
#pragma unroll
            for (int q = 0; q < 4; q++) acc[i][j][q] = 0.0f;

    auto load_tile = [&](int kt, int s) {
        long long ko = (long long)kt * BK;
        cp16(&As[s][lr * STR + lc],        Ag + (long long)lr * lda + ko + lc);
        cp16(&As[s][(lr + 64) * STR + lc], Ag + (long long)(lr + 64) * lda + ko + lc);
        cp16(&Bs[s][lr * STR + lc],        Bg + (long long)lr * ldb + ko + lc);
        if (BN == 128)
            cp16(&Bs[s][(lr + 64) * STR + lc], Bg + (long long)(lr + 64) * ldb + ko + lc);
    };

    int KT = K / BK;
    load_tile(0, 0);
    CP_COMMIT();

    for (int kt = 0; kt < KT; kt++) {
        if (kt + 1 < KT) load_tile(kt + 1, (kt + 1) & 1);
        CP_COMMIT();
        CP_WAIT(1);
        __syncthreads();

        const float* as = As[kt & 1];
        const float* bs = Bs[kt & 1];

#pragma unroll
        for (int kh = 0; kh < 2; kh++) {
            int kk = kh * 8;
            uint32_t af[4][4];
#pragma unroll
            for (int i = 0; i < 4; i++) {
                int r = wm * 64 + i * 16 + g;
                af[i][0] = bits(as[r * STR + kk + tg]);
                af[i][1] = bits(as[(r + 8) * STR + kk + tg]);
                af[i][2] = bits(as[r * STR + kk + tg + 4]);
                af[i][3] = bits(as[(r + 8) * STR + kk + tg + 4]);
            }
            uint32_t bf[TNT][2];
#pragma unroll
            for (int j = 0; j < TNT; j++) {
                int n = wn * TNW + j * 8 + g;
                bf[j][0] = bits(bs[n * STR + kk + tg]);
                bf[j][1] = bits(bs[n * STR + kk + tg + 4]);
            }
#pragma unroll
            for (int i = 0; i < 4; i++)
#pragma unroll
                for (int j = 0; j < TNT; j++)
                    mma_tf32(acc[i][j], af[i][0], af[i][1], af[i][2], af[i][3],
                             bf[j][0], bf[j][1]);
        }
        __syncthreads();
    }

#pragma unroll
    for (int i = 0; i < 4; i++) {
        int rl0 = blockIdx.y * BM + wm * 64 + i * 16 + g;
        long long r0 = rl0;
        if (EXPSTATS) {
            float s0 = 0.0f, s1 = 0.0f;
#pragma unroll
            for (int j = 0; j < TNT; j++) {
                s0 += __expf(alpha * acc[i][j][0]) + __expf(alpha * acc[i][j][1]);
                s1 += __expf(alpha * acc[i][j][2]) + __expf(alpha * acc[i][j][3]);
            }
            s0 += __shfl_xor_sync(0xffffffffu, s0, 1);
            s0 += __shfl_xor_sync(0xffffffffu, s0, 2);
            s1 += __shfl_xor_sync(0xffffffffu, s1, 1);
            s1 += __shfl_xor_sync(0xffffffffu, s1, 2);
            if (tg == 0) {
                atomicAdd(&lbuf[rl0],     s0);
                atomicAdd(&lbuf[rl0 + 8], s1);
            }
        } else {
#pragma unroll
            for (int j = 0; j < TNT; j++) {
                int col = blockIdx.x * BN + wn * TNW + j * 8 + tg * 2;
                float v0 = alpha * acc[i][j][0], v1 = alpha * acc[i][j][1];
                float v2 = alpha * acc[i][j][2], v3 = alpha * acc[i][j][3];
                if (RNDOUT) { v0 = tf32r(v0); v1 = tf32r(v1); v2 = tf32r(v2); v3 = tf32r(v3); }
                *(float2*)(C + r0 * ldc + col)       = make_float2(v0, v1);
                *(float2*)(C + (r0 + 8) * ldc + col) = make_float2(v2, v3);
            }
        }
    }
}

// ---------------- projection kernels ---------------------------------------
__global__ void __launch_bounds__(256)
qkv_proj(const float* __restrict__ xr, const float* __restrict__ wr,
         float* __restrict__ q, float* __restrict__ k, float* __restrict__ v)
{
    const float* B = wr + (long long)blockIdx.z * D_MODEL * D_MODEL;
    float*       C = (blockIdx.z == 0) ? q : (blockIdx.z == 1) ? k : v;
    gemm_nt_core<128, false, true>(xr, D_MODEL, B, D_MODEL, C, D_MODEL,
                                   D_MODEL, 1.0f, nullptr);
}

__global__ void __launch_bounds__(256)
out_proj(const float* __restrict__ ctx, const float* __restrict__ wr,
         float* __restrict__ o)
{
    gemm_nt_core<128, false, false>(ctx, D_MODEL, wr + 3LL * D_MODEL * D_MODEL,
                                    D_MODEL, o, D_MODEL, D_MODEL, 1.0f, nullptr);
}

// ---------------- stats: l[row] = sum exp(QK^T/8); no stores ---------------
__global__ void __launch_bounds__(256)
scores_stats(const float* __restrict__ q, const float* __restrict__ k,
             float* __restrict__ l)
{
    int z = blockIdx.z, zb = z >> 4, zh = z & 15;
    const long long SBH = (long long)SEQ * D_MODEL;
    gemm_nt_core<128, true, false>(
        q + (long long)zb * SBH + (long long)zh * DK, D_MODEL,
        k + (long long)zb * SBH + (long long)zh * DK, D_MODEL,
        nullptr, 0, DK, 0.125f,
        l + (long long)z * SEQ);
}

// ---------------- fused: recompute S, emit attn, ctx = P@V -----------------
// 512 threads = 16 warps (8 m-strips x 2 n-halves), 1 CTA/SM.
// K/V double-buffered, distance-1 cp.async pipeline.
// smem: Q[128x68] K[2][64x68] V[2][64x68] P[128x68] invl[128] = 139,792 B
#define TSTR 68
#define AC_SMEM ((128*TSTR + 4*64*TSTR + 128*TSTR + 128) * 4)

__global__ void __launch_bounds__(512)
attn_ctx(const float* __restrict__ Qg, const float* __restrict__ Kg,
         const float* __restrict__ Vg, const float* __restrict__ lsum,
         float* __restrict__ attn, float* __restrict__ ctx)
{
    extern __shared__ float sm[];
    float* Qs  = sm;                       // 128 x 68
    float* Ks0 = Qs  + 128 * TSTR;         // 64 x 68
    float* Ks1 = Ks0 + 64 * TSTR;
    float* Vs0 = Ks1 + 64 * TSTR;
    float* Vs1 = Vs0 + 64 * TSTR;
    float* Ps  = Vs1 + 64 * TSTR;          // 128 x 68
    float* invl = Ps + 128 * TSTR;         // 128

    int bh = blockIdx.y, b = bh >> 4, h = bh & 15;
    int q0 = blockIdx.x * 128;
    const float* qb = Qg + (long long)b * SEQ * D_MODEL + h * DK;
    const float* kb = Kg + (long long)b * SEQ * D_MODEL + h * DK;
    const float* vb = Vg + (long long)b * SEQ * D_MODEL + h * DK;
    float* at_b = attn + ((long long)bh * SEQ + q0) * SEQ;

    int t = threadIdx.x, w = t >> 5, lane = t & 31;
    int g = lane >> 2, tg = lane & 3;
    int wm = w & 7, wn = w >> 3;           // m-strip 0..7, n-half 0/1
    int r0 = wm * 16 + g, r1 = r0 + 8;

    auto loadKV = [&](int kt, float* Kd, float* Vd) {
        int s0 = kt * 64;
#pragma unroll
        for (int i = t; i < 1024; i += 512) {   // 64x64 f32 = 1024 float4 each
            int r = i >> 4, c4 = (i & 15) * 4;
            cp16(&Kd[r * TSTR + c4], kb + (long long)(s0 + r) * D_MODEL + c4);
            cp16(&Vd[r * TSTR + c4], vb + (long long)(s0 + r) * D_MODEL + c4);
        }
    };

    // Q tile (group 1), K0/V0 (group 2)
#pragma unroll
    for (int i = t; i < 2048; i += 512) {
        int r = i >> 4, c4 = (i & 15) * 4;
        cp16(&Qs[r * TSTR + c4], qb + (long long)(q0 + r) * D_MODEL + c4);
    }
    CP_COMMIT();
    loadKV(0, Ks0, Vs0);
    CP_COMMIT();
    if (t < 128) invl[t] = 1.0f / lsum[(long long)bh * SEQ + q0 + t];

    float d[4][4];
#pragma unroll
    for (int j = 0; j < 4; j++)
#pragma unroll
        for (int q = 0; q < 4; q++) d[j][q] = 0.0f;

    for (int kt = 0; kt < 32; kt++) {
        float* Kc = (kt & 1) ? Ks1 : Ks0;
        float* Vc = (kt & 1) ? Vs1 : Vs0;
        if (kt < 31) {
            loadKV(kt + 1, (kt & 1) ? Ks0 : Ks1, (kt & 1) ? Vs0 : Vs1);
            CP_COMMIT();
            CP_WAIT(1);
        } else {
            CP_WAIT(0);
        }
        __syncthreads();

        // S = Q(strip) @ K^T, this warp's 32-col half
        float c[4][4];
#pragma unroll
        for (int j = 0; j < 4; j++)
#pragma unroll
            for (int q = 0; q < 4; q++) c[j][q] = 0.0f;
#pragma unroll
        for (int ks = 0; ks < 8; ks++) {
            int k0 = ks * 8;
            uint32_t a0 = bits(Qs[r0 * TSTR + k0 + tg]);
            uint32_t a1 = bits(Qs[r1 * TSTR + k0 + tg]);
            uint32_t a2 = bits(Qs[r0 * TSTR + k0 + tg + 4]);
            uint32_t a3 = bits(Qs[r1 * TSTR + k0 + tg + 4]);
#pragma unroll
            for (int j = 0; j < 4; j++) {
                int n = wn * 32 + j * 8 + g;
                uint32_t b0 = bits(Kc[n * TSTR + k0 + tg]);
                uint32_t b1 = bits(Kc[n * TSTR + k0 + tg + 4]);
                mma_tf32(c[j], a0, a1, a2, a3, b0, b1);
            }
        }

        // exp -> tf32 round -> Ps
#pragma unroll
        for (int j = 0; j < 4; j++) {
            int col = wn * 32 + j * 8 + 2 * tg;
            float e0 = tf32r(__expf(c[j][0] * 0.125f));
            float e1 = tf32r(__expf(c[j][1] * 0.125f));
            float e2 = tf32r(__expf(c[j][2] * 0.125f));
            float e3 = tf32r(__expf(c[j][3] * 0.125f));
            *(float2*)&Ps[r0 * TSTR + col] = make_float2(e0, e1);
            *(float2*)&Ps[r1 * TSTR + col] = make_float2(e2, e3);
        }
        __syncthreads();

        // attn emit (overlaps PV MMA issue): p = expP * invl
        {
            int s0 = kt * 64;
#pragma unroll
            for (int i = t; i < 2048; i += 512) {
                int r = i >> 4, c4 = (i & 15) * 4;
                float4 p = *(const float4*)&Ps[r * TSTR + c4];
                float iv = invl[r];
                p.x *= iv; p.y *= iv; p.z *= iv; p.w *= iv;
                __stcs((float4*)(at_b + (long long)r * SEQ + s0 + c4), p);
            }
        }

        // ctx += expP @ V  (A from Ps raw bits, B col-fragments from Vc)
#pragma unroll
        for (int ks = 0; ks < 8; ks++) {
            int k0 = ks * 8;
            uint32_t a0 = bits(Ps[r0 * TSTR + k0 + tg]);
            uint32_t a1 = bits(Ps[r1 * TSTR + k0 + tg]);
            uint32_t a2 = bits(Ps[r0 * TSTR + k0 + tg + 4]);
            uint32_t a3 = bits(Ps[r1 * TSTR + k0 + tg + 4]);
#pragma unroll
            for (int j = 0; j < 4; j++) {
                int n = wn * 32 + j * 8 + g;
                uint32_t b0 = bits(Vc[(k0 + tg) * TSTR + n]);
                uint32_t b1 = bits(Vc[(k0 + tg + 4) * TSTR + n]);
                mma_tf32(d[j], a0, a1, a2, a3, b0, b1);
            }
        }
        __syncthreads();   // Ps/K/V reuse fence
    }

    // ctx epilogue: scale by invl, round (out_proj consumes raw bits)
    float* cb = ctx + ((long long)b * SEQ + q0) * D_MODEL + h * DK;
    float iv0 = invl[r0], iv1 = invl[r1];
#pragma unroll
    for (int j = 0; j < 4; j++) {
        int col = wn * 32 + j * 8 + 2 * tg;
        *(float2*)(cb + (long long)r0 * D_MODEL + col) =
            make_float2(tf32r(d[j][0] * iv0), tf32r(d[j][1] * iv0));
        *(float2*)(cb + (long long)r1 * D_MODEL + col) =
            make_float2(tf32r(d[j][2] * iv1), tf32r(d[j][3] * iv1));
    }
}

// ---------------- bias + residual + LayerNorm ------------------------------
__global__ void __launch_bounds__(256)
bias_res_ln(const float* __restrict__ o, const float* __restrict__ x,
            const float* __restrict__ bo, const float* __restrict__ gamma,
            const float* __restrict__ beta, float* __restrict__ y)
{
    long long row = blockIdx.x;
    int tid = threadIdx.x;
    const float4* o4 = (const float4*)(o + row * D_MODEL);
    const float4* x4 = (const float4*)(x + row * D_MODEL);
    const float4* b4 = (const float4*)bo;
    const float4* g4 = (const float4*)gamma;
    const float4* be4 = (const float4*)beta;

    float4 ov = o4[tid], xv = x4[tid], bv = b4[tid];
    float4 v;
    v.x = ov.x + xv.x + bv.x;
    v.y = ov.y + xv.y + bv.y;
    v.z = ov.z + xv.z + bv.z;
    v.w = ov.w + xv.w + bv.w;

    float s  = v.x + v.y + v.z + v.w;
    float sq = v.x * v.x + v.y * v.y + v.z * v.z + v.w * v.w;
    s  = blockReduceSum(s);
    sq = blockReduceSum(sq);

    float mean = s * (1.0f / D_MODEL);
    float var  = sq * (1.0f / D_MODEL) - mean * mean;
    float rstd = rsqrtf(var + LN_EPS);

    float4 gv = g4[tid], bev = be4[tid];
    float4 r;
    r.x = (v.x - mean) * rstd * gv.x + bev.x;
    r.y = (v.y - mean) * rstd * gv.y + bev.y;
    r.z = (v.z - mean) * rstd * gv.z + bev.z;
    r.w = (v.w - mean) * rstd * gv.w + bev.w;
    ((float4*)(y + row * D_MODEL))[tid] = r;
}

// ---------------- launch ---------------------------------------------------
extern "C" void kernel_launch(void* const* d_in, const int* in_sizes, int n_in,
                              void* d_out, int out_size)
{
    const float* x     = (const float*)d_in[0];
    const float* Wq    = (const float*)d_in[1];
    const float* Wk    = (const float*)d_in[2];
    const float* Wv    = (const float*)d_in[3];
    const float* Wo    = (const float*)d_in[4];
    const float* bo    = (const float*)d_in[5];
    const float* gamma = (const float*)d_in[6];
    const float* beta  = (const float*)d_in[7];

    float* y_out    = (float*)d_out;
    float* attn_out = nullptr;
    if ((long long)out_size >= SY + SA) {
        attn_out = y_out + SY;                 // outputs concatenated: y, attn
    } else if ((long long)out_size == SA) {
        attn_out = y_out;                      // attn-only output
        y_out = nullptr;
    }

    float *q, *k, *v, *ctx, *ob, *xr, *wr, *sc, *lptr;
    cudaGetSymbolAddress((void**)&q,    g_q);
    cudaGetSymbolAddress((void**)&k,    g_k);
    cudaGetSymbolAddress((void**)&v,    g_v);
    cudaGetSymbolAddress((void**)&ctx,  g_ctx);
    cudaGetSymbolAddress((void**)&ob,   g_o);
    cudaGetSymbolAddress((void**)&xr,   g_xr);
    cudaGetSymbolAddress((void**)&wr,   g_wr);
    cudaGetSymbolAddress((void**)&sc,   g_sc);
    cudaGetSymbolAddress((void**)&lptr, g_l);

    float* attn = attn_out ? attn_out : sc;

    static int smem_set = 0;
    if (!smem_set) {
        cudaFuncSetAttribute(attn_ctx,
            cudaFuncAttributeMaxDynamicSharedMemorySize, AC_SMEM);
        smem_set = 1;
    }

    cudaMemsetAsync(lptr, 0, (size_t)BH * SEQ * sizeof(float));

    // pre-round x + all weights (single launch)
    round_all<<<2048, 256>>>((const float4*)x, (const float4*)Wq,
                             (const float4*)Wk, (const float4*)Wv,
                             (const float4*)Wo, (float4*)xr, (float4*)wr);

    // Q/K/V projections (rounded outputs)
    qkv_proj<<<dim3(8, 32, 3), 256>>>(xr, wr, q, k, v);

    // row sums only (no 512 MB score store)
    scores_stats<<<dim3(16, 16, BH), 256>>>(q, k, lptr);

    // recompute S, emit normalized attn once, ctx = P @ V
    attn_ctx<<<dim3(16, BH), 512, AC_SMEM>>>(q, k, v, lptr, attn, ctx);

    if (y_out) {
        out_proj<<<dim3(8, 32), 256>>>(ctx, wr, ob);
        bias_res_ln<<<ROWS, 256>>>(ob, x, bo, gamma, beta, y_out);
    }
}

// round 12
// speedup vs baseline: 1.4509x; 1.4509x over previous
#include <cuda_runtime.h>
#include <cuda_fp16.h>
#include <cstdint>

#define D_MODEL 1024
#define N_HEADS 16
#define DK      64
#define SEQ     2048
#define BATCH   2
#define ROWS    (BATCH * SEQ)          /* 4096 */
#define BH      (BATCH * N_HEADS)      /* 32 */
#define LN_EPS  1e-5f

#define SY ((long long)ROWS * D_MODEL)                         /* 4194304  */
#define SA ((long long)BH * SEQ * SEQ)                         /* 134217728 */

// ---------------- scratch (static device globals: no runtime alloc) --------
__device__ __half g_q  [ROWS * D_MODEL];              // fp16 Q
__device__ __half g_k  [ROWS * D_MODEL];              // fp16 K
__device__ __half g_v  [ROWS * D_MODEL];              // fp16 V
__device__ __half g_vt [ROWS * D_MODEL];              // fp16 V^T per head
__device__ __half g_sch[(size_t)BH * SEQ * SEQ];      // fp16 exp-scores 256MB
__device__ float  g_ctx[ROWS * D_MODEL];
__device__ float  g_o  [ROWS * D_MODEL];
__device__ float  g_xr [ROWS * D_MODEL];              // tf32-rounded x
__device__ float  g_wr [4 * D_MODEL * D_MODEL];       // tf32-rounded weights
__device__ float  g_sc [(size_t)BH * SEQ * SEQ];      // f32 attn fallback
__device__ float  g_l  [BH * SEQ];                    // row sums of exp

// ---------------- helpers --------------------------------------------------
__device__ __forceinline__ float tf32r(float f) {
    uint32_t u;
    asm("cvt.rna.tf32.f32 %0, %1;" : "=r"(u) : "f"(f));
    return __uint_as_float(u);
}
__device__ __forceinline__ uint32_t bits(float f) { return __float_as_uint(f); }

__device__ __forceinline__ void cp16(void* smem, const void* g) {
    uint32_t a = (uint32_t)__cvta_generic_to_shared(smem);
    asm volatile("cp.async.cg.shared.global [%0], [%1], 16;" :: "r"(a), "l"(g));
}
#define CP_COMMIT()  asm volatile("cp.async.commit_group;")
#define CP_WAIT(n)   asm volatile("cp.async.wait_group %0;" :: "n"(n))

__device__ __forceinline__ void mma_tf32(float c[4],
    uint32_t a0, uint32_t a1, uint32_t a2, uint32_t a3,
    uint32_t b0, uint32_t b1)
{
    asm volatile(
        "mma.sync.aligned.m16n8k8.row.col.f32.tf32.tf32.f32 "
        "{%0,%1,%2,%3}, {%4,%5,%6,%7}, {%8,%9}, {%0,%1,%2,%3};"
        : "+f"(c[0]), "+f"(c[1]), "+f"(c[2]), "+f"(c[3])
        : "r"(a0), "r"(a1), "r"(a2), "r"(a3), "r"(b0), "r"(b1));
}
// fp16 MMA, f32 accumulate, K=16
__device__ __forceinline__ void mma_f16(float c[4],
    uint32_t a0, uint32_t a1, uint32_t a2, uint32_t a3,
    uint32_t b0, uint32_t b1)
{
    asm volatile(
        "mma.sync.aligned.m16n8k16.row.col.f32.f16.f16.f32 "
        "{%0,%1,%2,%3}, {%4,%5,%6,%7}, {%8,%9}, {%0,%1,%2,%3};"
        : "+f"(c[0]), "+f"(c[1]), "+f"(c[2]), "+f"(c[3])
        : "r"(a0), "r"(a1), "r"(a2), "r"(a3), "r"(b0), "r"(b1));
}

__device__ __forceinline__ float warpReduceSum(float v) {
#pragma unroll
    for (int o = 16; o > 0; o >>= 1) v += __shfl_xor_sync(0xffffffffu, v, o);
    return v;
}
__device__ __forceinline__ float blockReduceSum(float v) {
    __shared__ float sh[8];
    __shared__ float res;
    int lane = threadIdx.x & 31, w = threadIdx.x >> 5;
    v = warpReduceSum(v);
    if (lane == 0) sh[w] = v;
    __syncthreads();
    if (w == 0) {
        float t = (lane < 8) ? sh[lane] : 0.0f;
        t = warpReduceSum(t);
        if (lane == 0) res = t;
    }
    __syncthreads();
    float r = res;
    __syncthreads();
    return r;
}

// ---------------- merged tf32-RNA rounding (x + 4 weights) -----------------
#define NX4 ((int)(SY / 4))
#define NW4 (D_MODEL * D_MODEL / 4)
__global__ void __launch_bounds__(256)
round_all(const float4* __restrict__ x,
          const float4* __restrict__ Wq, const float4* __restrict__ Wk,
          const float4* __restrict__ Wv, const float4* __restrict__ Wo,
          float4* __restrict__ xr, float4* __restrict__ wr)
{
    int n4 = NX4 + 4 * NW4;
    for (int i = blockIdx.x * blockDim.x + threadIdx.x; i < n4;
         i += gridDim.x * blockDim.x) {
        const float4* src;
        float4* dst;
        if (i < NX4) { src = x + i; dst = xr + i; }
        else {
            int j = i - NX4;
            int ws = j / NW4, off = j - ws * NW4;
            src = (ws == 0 ? Wq : ws == 1 ? Wk : ws == 2 ? Wv : Wo) + off;
            dst = wr + (long long)ws * NW4 + off;
        }
        float4 v = *src;
        v.x = tf32r(v.x); v.y = tf32r(v.y); v.z = tf32r(v.z); v.w = tf32r(v.w);
        *dst = v;
    }
}

// ---------------- tf32 GEMM NT core (projections) --------------------------
// OUTMODE: 0 = f32, 1 = f32 tf32-rounded, 2 = fp16
template<int BN, int OUTMODE>
__device__ __forceinline__ void gemm_nt_core(
    const float* __restrict__ A, int lda,
    const float* __restrict__ B, int ldb,
    void* __restrict__ Cv, int ldc, int K)
{
    constexpr int BM  = 128;
    constexpr int BK  = 16;
    constexpr int STR = 20;
    constexpr int TNW = BN / 4;
    constexpr int TNT = BN / 32;

    __shared__ float As[2][BM * STR];
    __shared__ float Bs[2][BN * STR];

    int t    = threadIdx.x;
    int w    = t >> 5, lane = t & 31;
    int wm   = w >> 2, wn = w & 3;
    int g    = lane >> 2, tg = lane & 3;

    const float* Ag = A + (long long)(blockIdx.y * BM) * lda;
    const float* Bg = B + (long long)(blockIdx.x * BN) * ldb;

    int lr = t >> 2;
    int lc = (t & 3) * 4;

    float acc[4][TNT][4];
#pragma unroll
    for (int i = 0; i < 4; i++)
#pragma unroll
        for (int j = 0; j < TNT; j++)
#pragma unroll
            for (int q = 0; q < 4; q++) acc[i][j][q] = 0.0f;

    auto load_tile = [&](int kt, int s) {
        long long ko = (long long)kt * BK;
        cp16(&As[s][lr * STR + lc],        Ag + (long long)lr * lda + ko + lc);
        cp16(&As[s][(lr + 64) * STR + lc], Ag + (long long)(lr + 64) * lda + ko + lc);
        cp16(&Bs[s][lr * STR + lc],        Bg + (long long)lr * ldb + ko + lc);
        if (BN == 128)
            cp16(&Bs[s][(lr + 64) * STR + lc], Bg + (long long)(lr + 64) * ldb + ko + lc);
    };

    int KT = K / BK;
    load_tile(0, 0);
    CP_COMMIT();

    for (int kt = 0; kt < KT; kt++) {
        if (kt + 1 < KT) load_tile(kt + 1, (kt + 1) & 1);
        CP_COMMIT();
        CP_WAIT(1);
        __syncthreads();

        const float* as = As[kt & 1];
        const float* bs = Bs[kt & 1];

#pragma unroll
        for (int kh = 0; kh < 2; kh++) {
            int kk = kh * 8;
            uint32_t af[4][4];
#pragma unroll
            for (int i = 0; i < 4; i++) {
                int r = wm * 64 + i * 16 + g;
                af[i][0] = bits(as[r * STR + kk + tg]);
                af[i][1] = bits(as[(r + 8) * STR + kk + tg]);
                af[i][2] = bits(as[r * STR + kk + tg + 4]);
                af[i][3] = bits(as[(r + 8) * STR + kk + tg + 4]);
            }
            uint32_t bf[TNT][2];
#pragma unroll
            for (int j = 0; j < TNT; j++) {
                int n = wn * TNW + j * 8 + g;
                bf[j][0] = bits(bs[n * STR + kk + tg]);
                bf[j][1] = bits(bs[n * STR + kk + tg + 4]);
            }
#pragma unroll
            for (int i = 0; i < 4; i++)
#pragma unroll
                for (int j = 0; j < TNT; j++)
                    mma_tf32(acc[i][j], af[i][0], af[i][1], af[i][2], af[i][3],
                             bf[j][0], bf[j][1]);
        }
        __syncthreads();
    }

#pragma unroll
    for (int i = 0; i < 4; i++) {
        long long r0 = blockIdx.y * BM + wm * 64 + i * 16 + g;
#pragma unroll
        for (int j = 0; j < TNT; j++) {
            int col = blockIdx.x * BN + wn * TNW + j * 8 + tg * 2;
            float v0 = acc[i][j][0], v1 = acc[i][j][1];
            float v2 = acc[i][j][2], v3 = acc[i][j][3];
            if (OUTMODE == 2) {
                __half* C = (__half*)Cv;
                *(__half2*)(C + r0 * ldc + col) =
                    __floats2half2_rn(v0, v1);
                *(__half2*)(C + (r0 + 8) * ldc + col) =
                    __floats2half2_rn(v2, v3);
            } else {
                float* C = (float*)Cv;
                if (OUTMODE == 1) { v0 = tf32r(v0); v1 = tf32r(v1);
                                    v2 = tf32r(v2); v3 = tf32r(v3); }
                *(float2*)(C + r0 * ldc + col)       = make_float2(v0, v1);
                *(float2*)(C + (r0 + 8) * ldc + col) = make_float2(v2, v3);
            }
        }
    }
}

__global__ void __launch_bounds__(256)
qkv_proj(const float* __restrict__ xr, const float* __restrict__ wr,
         __half* __restrict__ q, __half* __restrict__ k, __half* __restrict__ v)
{
    const float* B = wr + (long long)blockIdx.z * D_MODEL * D_MODEL;
    __half*      C = (blockIdx.z == 0) ? q : (blockIdx.z == 1) ? k : v;
    gemm_nt_core<128, 2>(xr, D_MODEL, B, D_MODEL, C, D_MODEL, D_MODEL);
}

__global__ void __launch_bounds__(256)
out_proj(const float* __restrict__ ctx, const float* __restrict__ wr,
         float* __restrict__ o)
{
    gemm_nt_core<128, 0>(ctx, D_MODEL, wr + 3LL * D_MODEL * D_MODEL,
                         D_MODEL, o, D_MODEL, D_MODEL);
}

// ---------------- fp16 scores: sc = half(exp(QK^T/8)), l += rowsum ---------
// Block: 128q x 128k of one head. K=64 -> single-shot tile load, 4 MMA ksteps.
#define HS 72
__global__ void __launch_bounds__(256)
scores_exp_h(const __half* __restrict__ q, const __half* __restrict__ k,
             __half* __restrict__ sc, float* __restrict__ l)
{
    __shared__ __half Qs[128 * HS];
    __shared__ __half Ksm[128 * HS];

    int z = blockIdx.z, zb = z >> 4, zh = z & 15;
    const long long SBH = (long long)SEQ * D_MODEL;
    const __half* qb = q + (long long)zb * SBH + zh * DK
                         + (long long)(blockIdx.y * 128) * D_MODEL;
    const __half* kb = k + (long long)zb * SBH + zh * DK
                         + (long long)(blockIdx.x * 128) * D_MODEL;

    int t = threadIdx.x, w = t >> 5, lane = t & 31;
    int wm = w >> 2, wn = w & 3;
    int g = lane >> 2, tg = lane & 3;

    // 128 rows x 64 halves = 1024 16B-chunks each
#pragma unroll
    for (int i = t; i < 1024; i += 256) {
        int r = i >> 3, c8 = (i & 7) * 8;
        cp16(&Qs[r * HS + c8],  qb + (long long)r * D_MODEL + c8);
        cp16(&Ksm[r * HS + c8], kb + (long long)r * D_MODEL + c8);
    }
    CP_COMMIT();
    CP_WAIT(0);
    __syncthreads();

    float c[4][4][4];
#pragma unroll
    for (int i = 0; i < 4; i++)
#pragma unroll
        for (int j = 0; j < 4; j++)
#pragma unroll
            for (int qq = 0; qq < 4; qq++) c[i][j][qq] = 0.0f;

#pragma unroll
    for (int ks = 0; ks < 4; ks++) {
        int k0 = ks * 16;
        uint32_t af[4][4];
#pragma unroll
        for (int i = 0; i < 4; i++) {
            int r = wm * 64 + i * 16 + g;
            af[i][0] = *(const uint32_t*)&Qs[r * HS + k0 + 2 * tg];
            af[i][1] = *(const uint32_t*)&Qs[(r + 8) * HS + k0 + 2 * tg];
            af[i][2] = *(const uint32_t*)&Qs[r * HS + k0 + 8 + 2 * tg];
            af[i][3] = *(const uint32_t*)&Qs[(r + 8) * HS + k0 + 8 + 2 * tg];
        }
#pragma unroll
        for (int j = 0; j < 4; j++) {
            int n = wn * 32 + j * 8 + g;
            uint32_t b0 = *(const uint32_t*)&Ksm[n * HS + k0 + 2 * tg];
            uint32_t b1 = *(const uint32_t*)&Ksm[n * HS + k0 + 8 + 2 * tg];
#pragma unroll
            for (int i = 0; i < 4; i++)
                mma_f16(c[i][j], af[i][0], af[i][1], af[i][2], af[i][3], b0, b1);
        }
    }

    // epilogue: exp, store half, row sums
    __half* cb = sc + (long long)z * SEQ * SEQ
                    + (long long)(blockIdx.y * 128) * SEQ + blockIdx.x * 128;
    float* lb = l + (long long)z * SEQ + blockIdx.y * 128;
#pragma unroll
    for (int i = 0; i < 4; i++) {
        int rl = wm * 64 + i * 16 + g;
        float s0 = 0.0f, s1 = 0.0f;
#pragma unroll
        for (int j = 0; j < 4; j++) {
            float e0 = __expf(c[i][j][0] * 0.125f);
            float e1 = __expf(c[i][j][1] * 0.125f);
            float e2 = __expf(c[i][j][2] * 0.125f);
            float e3 = __expf(c[i][j][3] * 0.125f);
            int col = wn * 32 + j * 8 + 2 * tg;
            *(__half2*)(cb + (long long)rl * SEQ + col)       = __floats2half2_rn(e0, e1);
            *(__half2*)(cb + (long long)(rl + 8) * SEQ + col) = __floats2half2_rn(e2, e3);
            s0 += e0 + e1;
            s1 += e2 + e3;
        }
        s0 += __shfl_xor_sync(0xffffffffu, s0, 1);
        s0 += __shfl_xor_sync(0xffffffffu, s0, 2);
        s1 += __shfl_xor_sync(0xffffffffu, s1, 1);
        s1 += __shfl_xor_sync(0xffffffffu, s1, 2);
        if (tg == 0) {
            atomicAdd(&lb[rl],     s0);
            atomicAdd(&lb[rl + 8], s1);
        }
    }
}

// ---------------- per-head V transpose (fp16): Vt[bh][d][s] ----------------
__global__ void __launch_bounds__(256)
transpose_v_h(const __half* __restrict__ v, __half* __restrict__ vt)
{
    __shared__ __half tile[32][34];
    int bh = blockIdx.z;
    int b = bh >> 4, h = bh & 15;
    int s0 = blockIdx.x * 32, d0 = blockIdx.y * 32;
    int tx = threadIdx.x, ty = threadIdx.y;

    const __half* src = v + (long long)b * SEQ * D_MODEL + h * DK;
#pragma unroll
    for (int i = ty; i < 32; i += 8)
        tile[i][tx] = src[(long long)(s0 + i) * D_MODEL + d0 + tx];
    __syncthreads();
    __half* dst = vt + (long long)bh * DK * SEQ;
#pragma unroll
    for (int i = ty; i < 32; i += 8)
        dst[(long long)(d0 + i) * SEQ + s0 + tx] = tile[tx][i];
}

// ---------------- fused: attn emit + ctx = expP @ V (fp16 MMA) -------------
// 64-col double-buffered chunks; normalization decoupled (invl in epilogue).
// smem: As[2][128x72]h Bs[2][64x72]h invl[128]f = ~56 KB
#define FH 72
#define FC_SMEM ((2 * 128 * FH + 2 * 64 * FH) * 2 + 128 * 4)

__global__ void __launch_bounds__(256)
fused_ctx_h(const __half* __restrict__ expsc, const float* __restrict__ lsum,
            const __half* __restrict__ vt, float* __restrict__ attn,
            float* __restrict__ ctx)
{
    extern __shared__ char smraw[];
    __half* As0 = (__half*)smraw;               // 128 x 72
    __half* As1 = As0 + 128 * FH;
    __half* Bs0 = As1 + 128 * FH;               // 64 x 72
    __half* Bs1 = Bs0 + 64 * FH;
    float* invl = (float*)(Bs1 + 64 * FH);      // 128

    int bh = blockIdx.y, b = bh >> 4, h = bh & 15;
    int q0 = blockIdx.x * 128;

    const __half* sc_b = expsc + ((long long)bh * SEQ + q0) * SEQ;
    const __half* vt_b = vt + (long long)bh * DK * SEQ;
    float* at_b = attn + ((long long)bh * SEQ + q0) * SEQ;

    int t = threadIdx.x, w = t >> 5, lane = t & 31;
    int wm = w >> 2, wn = w & 3;               // 2x4 warps: m64 x n16 tiles
    int g = lane >> 2, tg = lane & 3;

    auto loadChunk = [&](__half* Ad, __half* Bd, int k0) {
#pragma unroll
        for (int i = t; i < 1024; i += 256) {          // A: 128x64 halves
            int r = i >> 3, c8 = (i & 7) * 8;
            cp16(&Ad[r * FH + c8], sc_b + (long long)r * SEQ + k0 + c8);
        }
#pragma unroll
        for (int i = t; i < 512; i += 256) {           // B: 64x64 halves
            int r = i >> 3, c8 = (i & 7) * 8;
            cp16(&Bd[r * FH + c8], vt_b + (long long)r * SEQ + k0 + c8);
        }
    };

    if (t < 128) invl[t] = 1.0f / lsum[(long long)bh * SEQ + q0 + t];

    float acc[4][2][4];
#pragma unroll
    for (int i = 0; i < 4; i++)
#pragma unroll
        for (int j = 0; j < 2; j++)
#pragma unroll
            for (int qq = 0; qq < 4; qq++) acc[i][j][qq] = 0.0f;

    loadChunk(As0, Bs0, 0);
    CP_COMMIT();
    __syncthreads();   // invl visible

    for (int kt = 0; kt < SEQ / 64; kt++) {
        int k0 = kt * 64;
        __half* as = (kt & 1) ? As1 : As0;
        __half* bs = (kt & 1) ? Bs1 : Bs0;

        if (kt < SEQ / 64 - 1) {
            loadChunk((kt & 1) ? As0 : As1, (kt & 1) ? Bs0 : Bs1, k0 + 64);
            CP_COMMIT();
            CP_WAIT(1);
        } else {
            CP_WAIT(0);
        }
        __syncthreads();

        // attn emit first (stores in flight during MMA): p = expP * invl
#pragma unroll
        for (int i = t; i < 1024; i += 256) {
            int r = i >> 3, c8 = (i & 7) * 8;
            float iv = invl[r];
            const __half2* ph = (const __half2*)&as[r * FH + c8];
            float* po = at_b + (long long)r * SEQ + k0 + c8;
            float4 o0, o1;
            float2 x0 = __half22float2(ph[0]);
            float2 x1 = __half22float2(ph[1]);
            float2 x2 = __half22float2(ph[2]);
            float2 x3 = __half22float2(ph[3]);
            o0.x = x0.x * iv; o0.y = x0.y * iv; o0.z = x1.x * iv; o0.w = x1.y * iv;
            o1.x = x2.x * iv; o1.y = x2.y * iv; o1.z = x3.x * iv; o1.w = x3.y * iv;
            __stcs((float4*)po, o0);
            __stcs((float4*)(po + 4), o1);
        }

        // ctx += expP @ Vt^T  (fp16 MMA, K=16 per step)
#pragma unroll
        for (int ks = 0; ks < 4; ks++) {
            int kk = ks * 16;
            uint32_t af[4][4];
#pragma unroll
            for (int i = 0; i < 4; i++) {
                int r = wm * 64 + i * 16 + g;
                af[i][0] = *(const uint32_t*)&as[r * FH + kk + 2 * tg];
                af[i][1] = *(const uint32_t*)&as[(r + 8) * FH + kk + 2 * tg];
                af[i][2] = *(const uint32_t*)&as[r * FH + kk + 8 + 2 * tg];
                af[i][3] = *(const uint32_t*)&as[(r + 8) * FH + kk + 8 + 2 * tg];
            }
#pragma unroll
            for (int j = 0; j < 2; j++) {
                int n = wn * 16 + j * 8 + g;
                uint32_t b0 = *(const uint32_t*)&bs[n * FH + kk + 2 * tg];
                uint32_t b1 = *(const uint32_t*)&bs[n * FH + kk + 8 + 2 * tg];
#pragma unroll
                for (int i = 0; i < 4; i++)
                    mma_f16(acc[i][j], af[i][0], af[i][1], af[i][2], af[i][3],
                            b0, b1);
            }
        }
        __syncthreads();   // before next iteration reuses buffers
    }

    // ctx epilogue: scale by invl, tf32-round (out_proj consumes raw bits)
    float* cb = ctx + ((long long)b * SEQ + q0) * D_MODEL + h * DK;
#pragma unroll
    for (int i = 0; i < 4; i++) {
        int r = wm * 64 + i * 16 + g;
        float iv0 = invl[r], iv1 = invl[r + 8];
#pragma unroll
        for (int j = 0; j < 2; j++) {
            int col = wn * 16 + j * 8 + tg * 2;
            *(float2*)(cb + (long long)r * D_MODEL + col) =
                make_float2(tf32r(acc[i][j][0] * iv0), tf32r(acc[i][j][1] * iv0));
            *(float2*)(cb + (long long)(r + 8) * D_MODEL + col) =
                make_float2(tf32r(acc[i][j][2] * iv1), tf32r(acc[i][j][3] * iv1));
        }
    }
}

// ---------------- bias + residual + LayerNorm ------------------------------
__global__ void __launch_bounds__(256)
bias_res_ln(const float* __restrict__ o, const float* __restrict__ x,
            const float* __restrict__ bo, const float* __restrict__ gamma,
            const float* __restrict__ beta, float* __restrict__ y)
{
    long long row = blockIdx.x;
    int tid = threadIdx.x;
    const float4* o4 = (const float4*)(o + row * D_MODEL);
    const float4* x4 = (const float4*)(x + row * D_MODEL);
    const float4* b4 = (const float4*)bo;
    const float4* g4 = (const float4*)gamma;
    const float4* be4 = (const float4*)beta;

    float4 ov = o4[tid], xv = x4[tid], bv = b4[tid];
    float4 v;
    v.x = ov.x + xv.x + bv.x;
    v.y = ov.y + xv.y + bv.y;
    v.z = ov.z + xv.z + bv.z;
    v.w = ov.w + xv.w + bv.w;

    float s  = v.x + v.y + v.z + v.w;
    float sq = v.x * v.x + v.y * v.y + v.z * v.z + v.w * v.w;
    s  = blockReduceSum(s);
    sq = blockReduceSum(sq);

    float mean = s * (1.0f / D_MODEL);
    float var  = sq * (1.0f / D_MODEL) - mean * mean;
    float rstd = rsqrtf(var + LN_EPS);

    float4 gv = g4[tid], bev = be4[tid];
    float4 r;
    r.x = (v.x - mean) * rstd * gv.x + bev.x;
    r.y = (v.y - mean) * rstd * gv.y + bev.y;
    r.z = (v.z - mean) * rstd * gv.z + bev.z;
    r.w = (v.w - mean) * rstd * gv.w + bev.w;
    ((float4*)(y + row * D_MODEL))[tid] = r;
}

// ---------------- launch ---------------------------------------------------
extern "C" void kernel_launch(void* const* d_in, const int* in_sizes, int n_in,
                              void* d_out, int out_size)
{
    const float* x     = (const float*)d_in[0];
    const float* Wq    = (const float*)d_in[1];
    const float* Wk    = (const float*)d_in[2];
    const float* Wv    = (const float*)d_in[3];
    const float* Wo    = (const float*)d_in[4];
    const float* bo    = (const float*)d_in[5];
    const float* gamma = (const float*)d_in[6];
    const float* beta  = (const float*)d_in[7];

    float* y_out    = (float*)d_out;
    float* attn_out = nullptr;
    if ((long long)out_size >= SY + SA) {
        attn_out = y_out + SY;                 // outputs concatenated: y, attn
    } else if ((long long)out_size == SA) {
        attn_out = y_out;                      // attn-only output
        y_out = nullptr;
    }

    __half *q, *k, *v, *vt, *sch;
    float *ctx, *ob, *xr, *wr, *scf, *lptr;
    cudaGetSymbolAddress((void**)&q,    g_q);
    cudaGetSymbolAddress((void**)&k,    g_k);
    cudaGetSymbolAddress((void**)&v,    g_v);
    cudaGetSymbolAddress((void**)&vt,   g_vt);
    cudaGetSymbolAddress((void**)&sch,  g_sch);
    cudaGetSymbolAddress((void**)&ctx,  g_ctx);
    cudaGetSymbolAddress((void**)&ob,   g_o);
    cudaGetSymbolAddress((void**)&xr,   g_xr);
    cudaGetSymbolAddress((void**)&wr,   g_wr);
    cudaGetSymbolAddress((void**)&scf,  g_sc);
    cudaGetSymbolAddress((void**)&lptr, g_l);

    float* attn = attn_out ? attn_out : scf;

    static int smem_set = 0;
    if (!smem_set) {
        cudaFuncSetAttribute(fused_ctx_h,
            cudaFuncAttributeMaxDynamicSharedMemorySize, FC_SMEM);
        smem_set = 1;
    }

    cudaMemsetAsync(lptr, 0, (size_t)BH * SEQ * sizeof(float));

    // pre-round x + weights (tf32 path for projections)
    round_all<<<2048, 256>>>((const float4*)x, (const float4*)Wq,
                             (const float4*)Wk, (const float4*)Wv,
                             (const float4*)Wo, (float4*)xr, (float4*)wr);

    // projections -> fp16 q,k,v
    qkv_proj<<<dim3(8, 32, 3), 256>>>(xr, wr, q, k, v);

    // fp16 exp-scores + f32 row sums
    scores_exp_h<<<dim3(16, 16, BH), 256>>>(q, k, sch, lptr);

    // fp16 V^T per head
    transpose_v_h<<<dim3(SEQ / 32, DK / 32, BH), dim3(32, 8)>>>(v, vt);

    // attn emit + ctx GEMM (fp16 MMA, async pipelined)
    fused_ctx_h<<<dim3(16, BH), 256, FC_SMEM>>>(sch, lptr, vt, attn, ctx);

    if (y_out) {
        out_proj<<<dim3(8, 32), 256>>>(ctx, wr, ob);
        bias_res_ln<<<ROWS, 256>>>(ob, x, bo, gamma, beta, y_out);
    }
}

// round 14
// speedup vs baseline: 1.7847x; 1.2300x over previous
#include <cuda_runtime.h>
#include <cuda_fp16.h>
#include <cstdint>

#define D_MODEL 1024
#define N_HEADS 16
#define DK      64
#define SEQ     2048
#define BATCH   2
#define ROWS    (BATCH * SEQ)          /* 4096 */
#define BH      (BATCH * N_HEADS)      /* 32 */
#define LN_EPS  1e-5f

#define SY ((long long)ROWS * D_MODEL)                         /* 4194304  */
#define SA ((long long)BH * SEQ * SEQ)                         /* 134217728 */

// ---------------- scratch (static device globals: no runtime alloc) --------
__device__ __half g_q  [ROWS * D_MODEL];              // fp16 Q
__device__ __half g_k  [ROWS * D_MODEL];              // fp16 K
__device__ __half g_v  [ROWS * D_MODEL];              // fp16 V
__device__ __half g_vt [ROWS * D_MODEL];              // fp16 V^T per head
__device__ __half g_xh [ROWS * D_MODEL];              // fp16 x
__device__ __half g_wh [4 * D_MODEL * D_MODEL];       // fp16 Wq,Wk,Wv,Wo
__device__ __half g_ch [ROWS * D_MODEL];              // fp16 ctx
__device__ __half g_sch[(size_t)BH * SEQ * SEQ];      // fp16 exp-scores 256MB
__device__ float  g_o  [ROWS * D_MODEL];
__device__ float  g_sc [(size_t)BH * SEQ * SEQ];      // f32 attn fallback
__device__ float  g_l  [BH * SEQ];                    // row sums of exp

// ---------------- helpers --------------------------------------------------
__device__ __forceinline__ void cp16(void* smem, const void* g) {
    uint32_t a = (uint32_t)__cvta_generic_to_shared(smem);
    asm volatile("cp.async.cg.shared.global [%0], [%1], 16;" :: "r"(a), "l"(g));
}
#define CP_COMMIT()  asm volatile("cp.async.commit_group;")
#define CP_WAIT(n)   asm volatile("cp.async.wait_group %0;" :: "n"(n))

// fp16 MMA, f32 accumulate, K=16
__device__ __forceinline__ void mma_f16(float c[4],
    uint32_t a0, uint32_t a1, uint32_t a2, uint32_t a3,
    uint32_t b0, uint32_t b1)
{
    asm volatile(
        "mma.sync.aligned.m16n8k16.row.col.f32.f16.f16.f32 "
        "{%0,%1,%2,%3}, {%4,%5,%6,%7}, {%8,%9}, {%0,%1,%2,%3};"
        : "+f"(c[0]), "+f"(c[1]), "+f"(c[2]), "+f"(c[3])
        : "r"(a0), "r"(a1), "r"(a2), "r"(a3), "r"(b0), "r"(b1));
}

__device__ __forceinline__ float warpReduceSum(float v) {
#pragma unroll
    for (int o = 16; o > 0; o >>= 1) v += __shfl_xor_sync(0xffffffffu, v, o);
    return v;
}
__device__ __forceinline__ float blockReduceSum(float v) {
    __shared__ float sh[8];
    __shared__ float res;
    int lane = threadIdx.x & 31, w = threadIdx.x >> 5;
    v = warpReduceSum(v);
    if (lane == 0) sh[w] = v;
    __syncthreads();
    if (w == 0) {
        float t = (lane < 8) ? sh[lane] : 0.0f;
        t = warpReduceSum(t);
        if (lane == 0) res = t;
    }
    __syncthreads();
    float r = res;
    __syncthreads();
    return r;
}

// ---------------- convert x + 4 weights to fp16 (one launch) ---------------
#define NX4 ((int)(SY / 4))
#define NW4 (D_MODEL * D_MODEL / 4)
__global__ void __launch_bounds__(256)
convert_h(const float4* __restrict__ x,
          const float4* __restrict__ Wq, const float4* __restrict__ Wk,
          const float4* __restrict__ Wv, const float4* __restrict__ Wo,
          __half2* __restrict__ xh, __half2* __restrict__ wh)
{
    int n4 = NX4 + 4 * NW4;
    for (int i = blockIdx.x * blockDim.x + threadIdx.x; i < n4;
         i += gridDim.x * blockDim.x) {
        const float4* src;
        __half2* dst;
        if (i < NX4) { src = x + i; dst = xh + 2 * (long long)i; }
        else {
            int j = i - NX4;
            int ws = j / NW4, off = j - ws * NW4;
            src = (ws == 0 ? Wq : ws == 1 ? Wk : ws == 2 ? Wv : Wo) + off;
            dst = wh + 2 * ((long long)ws * NW4 + off);
        }
        float4 v = *src;
        dst[0] = __floats2half2_rn(v.x, v.y);
        dst[1] = __floats2half2_rn(v.z, v.w);
    }
}

// ---------------- fp16 GEMM NT core (projections) --------------------------
// C[128 x 128 tile] = A[M,K] * B[N,K]^T. A,B fp16 row-major. f32 accum.
// BK=32 (2 fp16 ksteps/tile), double-buffered cp.async, 256 thr = 8 warps 2x4.
// OUTH: write fp16 C; else f32.
#define PSTRH 40
template<bool OUTH>
__device__ __forceinline__ void gemm_nt_h(
    const __half* __restrict__ A, int lda,
    const __half* __restrict__ B, int ldb,
    void* __restrict__ Cv, int ldc, int K)
{
    __shared__ __half As[2][128 * PSTRH];
    __shared__ __half Bs[2][128 * PSTRH];

    int t    = threadIdx.x;
    int w    = t >> 5, lane = t & 31;
    int wm   = w >> 2, wn = w & 3;
    int g    = lane >> 2, tg = lane & 3;

    const __half* Ag = A + (long long)(blockIdx.y * 128) * lda;
    const __half* Bg = B + (long long)(blockIdx.x * 128) * ldb;

    int lr = t >> 1;             // 0..127: row
    int lc = (t & 1) * 16;       // 0 or 16: half-offset (16 halves = 2 chunks)

    float acc[4][4][4];
#pragma unroll
    for (int i = 0; i < 4; i++)
#pragma unroll
        for (int j = 0; j < 4; j++)
#pragma unroll
            for (int q = 0; q < 4; q++) acc[i][j][q] = 0.0f;

    auto load_tile = [&](int kt, int s) {
        long long ko = (long long)kt * 32;
        cp16(&As[s][lr * PSTRH + lc],     Ag + (long long)lr * lda + ko + lc);
        cp16(&As[s][lr * PSTRH + lc + 8], Ag + (long long)lr * lda + ko + lc + 8);
        cp16(&Bs[s][lr * PSTRH + lc],     Bg + (long long)lr * ldb + ko + lc);
        cp16(&Bs[s][lr * PSTRH + lc + 8], Bg + (long long)lr * ldb + ko + lc + 8);
    };

    int KT = K / 32;
    load_tile(0, 0);
    CP_COMMIT();

    for (int kt = 0; kt < KT; kt++) {
        if (kt + 1 < KT) load_tile(kt + 1, (kt + 1) & 1);
        CP_COMMIT();
        CP_WAIT(1);
        __syncthreads();

        const __half* as = As[kt & 1];
        const __half* bs = Bs[kt & 1];

#pragma unroll
        for (int kh = 0; kh < 2; kh++) {
            int kk = kh * 16;
            uint32_t af[4][4];
#pragma unroll
            for (int i = 0; i < 4; i++) {
                int r = wm * 64 + i * 16 + g;
                af[i][0] = *(const uint32_t*)&as[r * PSTRH + kk + 2 * tg];
                af[i][1] = *(const uint32_t*)&as[(r + 8) * PSTRH + kk + 2 * tg];
                af[i][2] = *(const uint32_t*)&as[r * PSTRH + kk + 8 + 2 * tg];
                af[i][3] = *(const uint32_t*)&as[(r + 8) * PSTRH + kk + 8 + 2 * tg];
            }
            uint32_t bf[4][2];
#pragma unroll
            for (int j = 0; j < 4; j++) {
                int n = wn * 32 + j * 8 + g;
                bf[j][0] = *(const uint32_t*)&bs[n * PSTRH + kk + 2 * tg];
                bf[j][1] = *(const uint32_t*)&bs[n * PSTRH + kk + 8 + 2 * tg];
            }
#pragma unroll
            for (int i = 0; i < 4; i++)
#pragma unroll
                for (int j = 0; j < 4; j++)
                    mma_f16(acc[i][j], af[i][0], af[i][1], af[i][2], af[i][3],
                            bf[j][0], bf[j][1]);
        }
        __syncthreads();
    }

#pragma unroll
    for (int i = 0; i < 4; i++) {
        long long r0 = blockIdx.y * 128 + wm * 64 + i * 16 + g;
#pragma unroll
        for (int j = 0; j < 4; j++) {
            int col = blockIdx.x * 128 + wn * 32 + j * 8 + tg * 2;
            if (OUTH) {
                __half* C = (__half*)Cv;
                *(__half2*)(C + r0 * ldc + col) =
                    __floats2half2_rn(acc[i][j][0], acc[i][j][1]);
                *(__half2*)(C + (r0 + 8) * ldc + col) =
                    __floats2half2_rn(acc[i][j][2], acc[i][j][3]);
            } else {
                float* C = (float*)Cv;
                *(float2*)(C + r0 * ldc + col) =
                    make_float2(acc[i][j][0], acc[i][j][1]);
                *(float2*)(C + (r0 + 8) * ldc + col) =
                    make_float2(acc[i][j][2], acc[i][j][3]);
            }
        }
    }
}

__global__ void __launch_bounds__(256)
qkv_proj_h(const __half* __restrict__ xh, const __half* __restrict__ wh,
           __half* __restrict__ q, __half* __restrict__ k, __half* __restrict__ v)
{
    const __half* B = wh + (long long)blockIdx.z * D_MODEL * D_MODEL;
    __half*       C = (blockIdx.z == 0) ? q : (blockIdx.z == 1) ? k : v;
    gemm_nt_h<true>(xh, D_MODEL, B, D_MODEL, C, D_MODEL, D_MODEL);
}

__global__ void __launch_bounds__(256)
out_proj_h(const __half* __restrict__ ch, const __half* __restrict__ wh,
           float* __restrict__ o)
{
    gemm_nt_h<false>(ch, D_MODEL, wh + 3LL * D_MODEL * D_MODEL,
                     D_MODEL, o, D_MODEL, D_MODEL);
}

// ---------------- fp16 scores: sc = half(exp(QK^T/8)), l += rowsum ---------
#define HS 72
__global__ void __launch_bounds__(256)
scores_exp_h(const __half* __restrict__ q, const __half* __restrict__ k,
             __half* __restrict__ sc, float* __restrict__ l)
{
    __shared__ __half Qs[128 * HS];
    __shared__ __half Ksm[128 * HS];

    int z = blockIdx.z, zb = z >> 4, zh = z & 15;
    const long long SBH = (long long)SEQ * D_MODEL;
    const __half* qb = q + (long long)zb * SBH + zh * DK
                         + (long long)(blockIdx.y * 128) * D_MODEL;
    const __half* kb = k + (long long)zb * SBH + zh * DK
                         + (long long)(blockIdx.x * 128) * D_MODEL;

    int t = threadIdx.x, w = t >> 5, lane = t & 31;
    int wm = w >> 2, wn = w & 3;
    int g = lane >> 2, tg = lane & 3;

#pragma unroll
    for (int i = t; i < 1024; i += 256) {
        int r = i >> 3, c8 = (i & 7) * 8;
        cp16(&Qs[r * HS + c8],  qb + (long long)r * D_MODEL + c8);
        cp16(&Ksm[r * HS + c8], kb + (long long)r * D_MODEL + c8);
    }
    CP_COMMIT();
    CP_WAIT(0);
    __syncthreads();

    float c[4][4][4];
#pragma unroll
    for (int i = 0; i < 4; i++)
#pragma unroll
        for (int j = 0; j < 4; j++)
#pragma unroll
            for (int qq = 0; qq < 4; qq++) c[i][j][qq] = 0.0f;

#pragma unroll
    for (int ks = 0; ks < 4; ks++) {
        int k0 = ks * 16;
        uint32_t af[4][4];
#pragma unroll
        for (int i = 0; i < 4; i++) {
            int r = wm * 64 + i * 16 + g;
            af[i][0] = *(const uint32_t*)&Qs[r * HS + k0 + 2 * tg];
            af[i][1] = *(const uint32_t*)&Qs[(r + 8) * HS + k0 + 2 * tg];
            af[i][2] = *(const uint32_t*)&Qs[r * HS + k0 + 8 + 2 * tg];
            af[i][3] = *(const uint32_t*)&Qs[(r + 8) * HS + k0 + 8 + 2 * tg];
        }
#pragma unroll
        for (int j = 0; j < 4; j++) {
            int n = wn * 32 + j * 8 + g;
            uint32_t b0 = *(const uint32_t*)&Ksm[n * HS + k0 + 2 * tg];
            uint32_t b1 = *(const uint32_t*)&Ksm[n * HS + k0 + 8 + 2 * tg];
#pragma unroll
            for (int i = 0; i < 4; i++)
                mma_f16(c[i][j], af[i][0], af[i][1], af[i][2], af[i][3], b0, b1);
        }
    }

    __half* cb = sc + (long long)z * SEQ * SEQ
                    + (long long)(blockIdx.y * 128) * SEQ + blockIdx.x * 128;
    float* lb = l + (long long)z * SEQ + blockIdx.y * 128;
#pragma unroll
    for (int i = 0; i < 4; i++) {
        int rl = wm * 64 + i * 16 + g;
        float s0 = 0.0f, s1 = 0.0f;
#pragma unroll
        for (int j = 0; j < 4; j++) {
            float e0 = __expf(c[i][j][0] * 0.125f);
            float e1 = __expf(c[i][j][1] * 0.125f);
            float e2 = __expf(c[i][j][2] * 0.125f);
            float e3 = __expf(c[i][j][3] * 0.125f);
            int col = wn * 32 + j * 8 + 2 * tg;
            *(__half2*)(cb + (long long)rl * SEQ + col)       = __floats2half2_rn(e0, e1);
            *(__half2*)(cb + (long long)(rl + 8) * SEQ + col) = __floats2half2_rn(e2, e3);
            s0 += e0 + e1;
            s1 += e2 + e3;
        }
        s0 += __shfl_xor_sync(0xffffffffu, s0, 1);
        s0 += __shfl_xor_sync(0xffffffffu, s0, 2);
        s1 += __shfl_xor_sync(0xffffffffu, s1, 1);
        s1 += __shfl_xor_sync(0xffffffffu, s1, 2);
        if (tg == 0) {
            atomicAdd(&lb[rl],     s0);
            atomicAdd(&lb[rl + 8], s1);
        }
    }
}

// ---------------- per-head V transpose (fp16): Vt[bh][d][s] ----------------
__global__ void __launch_bounds__(256)
transpose_v_h(const __half* __restrict__ v, __half* __restrict__ vt)
{
    __shared__ __half tile[32][34];
    int bh = blockIdx.z;
    int b = bh >> 4, h = bh & 15;
    int s0 = blockIdx.x * 32, d0 = blockIdx.y * 32;
    int tx = threadIdx.x, ty = threadIdx.y;

    const __half* src = v + (long long)b * SEQ * D_MODEL + h * DK;
#pragma unroll
    for (int i = ty; i < 32; i += 8)
        tile[i][tx] = src[(long long)(s0 + i) * D_MODEL + d0 + tx];
    __syncthreads();
    __half* dst = vt + (long long)bh * DK * SEQ;
#pragma unroll
    for (int i = ty; i < 32; i += 8)
        dst[(long long)(d0 + i) * SEQ + s0 + tx] = tile[tx][i];
}

// ---------------- fused: attn emit + ctx = expP @ V (fp16 MMA) -------------
#define FH 72
#define FC_SMEM ((2 * 128 * FH + 2 * 64 * FH) * 2 + 128 * 4)

__global__ void __launch_bounds__(256)
fused_ctx_h(const __half* __restrict__ expsc, const float* __restrict__ lsum,
            const __half* __restrict__ vt, float* __restrict__ attn,
            __half* __restrict__ ctx)
{
    extern __shared__ char smraw[];
    __half* As0 = (__half*)smraw;               // 128 x 72
    __half* As1 = As0 + 128 * FH;
    __half* Bs0 = As1 + 128 * FH;               // 64 x 72
    __half* Bs1 = Bs0 + 64 * FH;
    float* invl = (float*)(Bs1 + 64 * FH);      // 128

    int bh = blockIdx.y, b = bh >> 4, h = bh & 15;
    int q0 = blockIdx.x * 128;

    const __half* sc_b = expsc + ((long long)bh * SEQ + q0) * SEQ;
    const __half* vt_b = vt + (long long)bh * DK * SEQ;
    float* at_b = attn + ((long long)bh * SEQ + q0) * SEQ;

    int t = threadIdx.x, w = t >> 5, lane = t & 31;
    int wm = w >> 2, wn = w & 3;               // 2x4 warps: m64 x n16 tiles
    int g = lane >> 2, tg = lane & 3;

    auto loadChunk = [&](__half* Ad, __half* Bd, int k0) {
#pragma unroll
        for (int i = t; i < 1024; i += 256) {          // A: 128x64 halves
            int r = i >> 3, c8 = (i & 7) * 8;
            cp16(&Ad[r * FH + c8], sc_b + (long long)r * SEQ + k0 + c8);
        }
#pragma unroll
        for (int i = t; i < 512; i += 256) {           // B: 64x64 halves
            int r = i >> 3, c8 = (i & 7) * 8;
            cp16(&Bd[r * FH + c8], vt_b + (long long)r * SEQ + k0 + c8);
        }
    };

    if (t < 128) invl[t] = 1.0f / lsum[(long long)bh * SEQ + q0 + t];

    float acc[4][2][4];
#pragma unroll
    for (int i = 0; i < 4; i++)
#pragma unroll
        for (int j = 0; j < 2; j++)
#pragma unroll
            for (int qq = 0; qq < 4; qq++) acc[i][j][qq] = 0.0f;

    loadChunk(As0, Bs0, 0);
    CP_COMMIT();
    __syncthreads();   // invl visible

    for (int kt = 0; kt < SEQ / 64; kt++) {
        int k0 = kt * 64;
        __half* as = (kt & 1) ? As1 : As0;
        __half* bs = (kt & 1) ? Bs1 : Bs0;

        if (kt < SEQ / 64 - 1) {
            loadChunk((kt & 1) ? As0 : As1, (kt & 1) ? Bs0 : Bs1, k0 + 64);
            CP_COMMIT();
            CP_WAIT(1);
        } else {
            CP_WAIT(0);
        }
        __syncthreads();

        // attn emit first (stores in flight during MMA): p = expP * invl
#pragma unroll
        for (int i = t; i < 1024; i += 256) {
            int r = i >> 3, c8 = (i & 7) * 8;
            float iv = invl[r];
            const __half2* ph = (const __half2*)&as[r * FH + c8];
            float* po = at_b + (long long)r * SEQ + k0 + c8;
            float4 o0, o1;
            float2 x0 = __half22float2(ph[0]);
            float2 x1 = __half22float2(ph[1]);
            float2 x2 = __half22float2(ph[2]);
            float2 x3 = __half22float2(ph[3]);
            o0.x = x0.x * iv; o0.y = x0.y * iv; o0.z = x1.x * iv; o0.w = x1.y * iv;
            o1.x = x2.x * iv; o1.y = x2.y * iv; o1.z = x3.x * iv; o1.w = x3.y * iv;
            __stcs((float4*)po, o0);
            __stcs((float4*)(po + 4), o1);
        }

        // ctx += expP @ Vt^T  (fp16 MMA, K=16 per step)
#pragma unroll
        for (int ks = 0; ks < 4; ks++) {
            int kk = ks * 16;
            uint32_t af[4][4];
#pragma unroll
            for (int i = 0; i < 4; i++) {
                int r = wm * 64 + i * 16 + g;
                af[i][0] = *(const uint32_t*)&as[r * FH + kk + 2 * tg];
                af[i][1] = *(const uint32_t*)&as[(r + 8) * FH + kk + 2 * tg];
                af[i][2] = *(const uint32_t*)&as[r * FH + kk + 8 + 2 * tg];
                af[i][3] = *(const uint32_t*)&as[(r + 8) * FH + kk + 8 + 2 * tg];
            }
#pragma unroll
            for (int j = 0; j < 2; j++) {
                int n = wn * 16 + j * 8 + g;
                uint32_t b0 = *(const uint32_t*)&bs[n * FH + kk + 2 * tg];
                uint32_t b1 = *(const uint32_t*)&bs[n * FH + kk + 8 + 2 * tg];
#pragma unroll
                for (int i = 0; i < 4; i++)
                    mma_f16(acc[i][j], af[i][0], af[i][1], af[i][2], af[i][3],
                            b0, b1);
            }
        }
        __syncthreads();   // before next iteration reuses buffers
    }

    // ctx epilogue: scale by invl, emit fp16 (out_proj consumes fp16)
    __half* cb = ctx + ((long long)b * SEQ + q0) * D_MODEL + h * DK;
#pragma unroll
    for (int i = 0; i < 4; i++) {
        int r = wm * 64 + i * 16 + g;
        float iv0 = invl[r], iv1 = invl[r + 8];
#pragma unroll
        for (int j = 0; j < 2; j++) {
            int col = wn * 16 + j * 8 + tg * 2;
            *(__half2*)(cb + (long long)r * D_MODEL + col) =
                __floats2half2_rn(acc[i][j][0] * iv0, acc[i][j][1] * iv0);
            *(__half2*)(cb + (long long)(r + 8) * D_MODEL + col) =
                __floats2half2_rn(acc[i][j][2] * iv1, acc[i][j][3] * iv1);
        }
    }
}

// ---------------- bias + residual + LayerNorm ------------------------------
__global__ void __launch_bounds__(256)
bias_res_ln(const float* __restrict__ o, const float* __restrict__ x,
            const float* __restrict__ bo, const float* __restrict__ gamma,
            const float* __restrict__ beta, float* __restrict__ y)
{
    long long row = blockIdx.x;
    int tid = threadIdx.x;
    const float4* o4 = (const float4*)(o + row * D_MODEL);
    const float4* x4 = (const float4*)(x + row * D_MODEL);
    const float4* b4 = (const float4*)bo;
    const float4* g4 = (const float4*)gamma;
    const float4* be4 = (const float4*)beta;

    float4 ov = o4[tid], xv = x4[tid], bv = b4[tid];
    float4 v;
    v.x = ov.x + xv.x + bv.x;
    v.y = ov.y + xv.y + bv.y;
    v.z = ov.z + xv.z + bv.z;
    v.w = ov.w + xv.w + bv.w;

    float s  = v.x + v.y + v.z + v.w;
    float sq = v.x * v.x + v.y * v.y + v.z * v.z + v.w * v.w;
    s  = blockReduceSum(s);
    sq = blockReduceSum(sq);

    float mean = s * (1.0f / D_MODEL);
    float var  = sq * (1.0f / D_MODEL) - mean * mean;
    float rstd = rsqrtf(var + LN_EPS);

    float4 gv = g4[tid], bev = be4[tid];
    float4 r;
    r.x = (v.x - mean) * rstd * gv.x + bev.x;
    r.y = (v.y - mean) * rstd * gv.y + bev.y;
    r.z = (v.z - mean) * rstd * gv.z + bev.z;
    r.w = (v.w - mean) * rstd * gv.w + bev.w;
    ((float4*)(y + row * D_MODEL))[tid] = r;
}

// ---------------- launch ---------------------------------------------------
extern "C" void kernel_launch(void* const* d_in, const int* in_sizes, int n_in,
                              void* d_out, int out_size)
{
    const float* x     = (const float*)d_in[0];
    const float* Wq    = (const float*)d_in[1];
    const float* Wk    = (const float*)d_in[2];
    const float* Wv    = (const float*)d_in[3];
    const float* Wo    = (const float*)d_in[4];
    const float* bo    = (const float*)d_in[5];
    const float* gamma = (const float*)d_in[6];
    const float* beta  = (const float*)d_in[7];

    float* y_out    = (float*)d_out;
    float* attn_out = nullptr;
    if ((long long)out_size >= SY + SA) {
        attn_out = y_out + SY;                 // outputs concatenated: y, attn
    } else if ((long long)out_size == SA) {
        attn_out = y_out;                      // attn-only output
        y_out = nullptr;
    }

    __half *q, *k, *v, *vt, *xh, *wh, *ch, *sch;
    float *ob, *scf, *lptr;
    cudaGetSymbolAddress((void**)&q,    g_q);
    cudaGetSymbolAddress((void**)&k,    g_k);
    cudaGetSymbolAddress((void**)&v,    g_v);
    cudaGetSymbolAddress((void**)&vt,   g_vt);
    cudaGetSymbolAddress((void**)&xh,   g_xh);
    cudaGetSymbolAddress((void**)&wh,   g_wh);
    cudaGetSymbolAddress((void**)&ch,   g_ch);
    cudaGetSymbolAddress((void**)&sch,  g_sch);
    cudaGetSymbolAddress((void**)&ob,   g_o);
    cudaGetSymbolAddress((void**)&scf,  g_sc);
    cudaGetSymbolAddress((void**)&lptr, g_l);

    float* attn = attn_out ? attn_out : scf;

    static int smem_set = 0;
    if (!smem_set) {
        cudaFuncSetAttribute(fused_ctx_h,
            cudaFuncAttributeMaxDynamicSharedMemorySize, FC_SMEM);
        smem_set = 1;
    }

    cudaMemsetAsync(lptr, 0, (size_t)BH * SEQ * sizeof(float));

    // convert x + weights to fp16 (single launch)
    convert_h<<<2048, 256>>>((const float4*)x, (const float4*)Wq,
                             (const float4*)Wk, (const float4*)Wv,
                             (const float4*)Wo, (__half2*)xh, (__half2*)wh);

    // projections (fp16 MMA) -> fp16 q,k,v
    qkv_proj_h<<<dim3(8, 32, 3), 256>>>(xh, wh, q, k, v);

    // fp16 exp-scores + f32 row sums
    scores_exp_h<<<dim3(16, 16, BH), 256>>>(q, k, sch, lptr);

    // fp16 V^T per head
    transpose_v_h<<<dim3(SEQ / 32, DK / 32, BH), dim3(32, 8)>>>(v, vt);

    // attn emit + ctx GEMM (fp16 MMA, async pipelined) -> fp16 ctx
    fused_ctx_h<<<dim3(16, BH), 256, FC_SMEM>>>(sch, lptr, vt, attn, ch);

    if (y_out) {
        out_proj_h<<<dim3(8, 32), 256>>>(ch, wh, ob);
        bias_res_ln<<<ROWS, 256>>>(ob, x, bo, gamma, beta, y_out);
    }
}

// round 15
// speedup vs baseline: 1.8129x; 1.0158x over previous
#include <cuda_runtime.h>
#include <cuda_fp16.h>
#include <cstdint>

#define D_MODEL 1024
#define N_HEADS 16
#define DK      64
#define SEQ     2048
#define BATCH   2
#define ROWS    (BATCH * SEQ)          /* 4096 */
#define BH      (BATCH * N_HEADS)      /* 32 */
#define LN_EPS  1e-5f

#define SY ((long long)ROWS * D_MODEL)                         /* 4194304  */
#define SA ((long long)BH * SEQ * SEQ)                         /* 134217728 */

// ---------------- scratch (static device globals: no runtime alloc) --------
__device__ __half g_q  [ROWS * D_MODEL];              // fp16 Q
__device__ __half g_k  [ROWS * D_MODEL];              // fp16 K
__device__ __half g_v  [ROWS * D_MODEL];              // fp16 V
__device__ __half g_vt [ROWS * D_MODEL];              // fp16 V^T per head
__device__ __half g_xh [ROWS * D_MODEL];              // fp16 x
__device__ __half g_wh [4 * D_MODEL * D_MODEL];       // fp16 Wq,Wk,Wv,Wo
__device__ __half g_ch [ROWS * D_MODEL];              // fp16 ctx
__device__ __half g_sch[(size_t)BH * SEQ * SEQ];      // fp16 exp-scores 256MB
__device__ float  g_o  [ROWS * D_MODEL];
__device__ float  g_sc [(size_t)BH * SEQ * SEQ];      // f32 attn fallback
__device__ float  g_l  [BH * SEQ];                    // row sums of exp

// ---------------- helpers --------------------------------------------------
__device__ __forceinline__ void cp16(void* smem, const void* g) {
    uint32_t a = (uint32_t)__cvta_generic_to_shared(smem);
    asm volatile("cp.async.cg.shared.global [%0], [%1], 16;" :: "r"(a), "l"(g));
}
#define CP_COMMIT()  asm volatile("cp.async.commit_group;")
#define CP_WAIT(n)   asm volatile("cp.async.wait_group %0;" :: "n"(n))

// fp16 MMA, f32 accumulate, K=16
__device__ __forceinline__ void mma_f16(float c[4],
    uint32_t a0, uint32_t a1, uint32_t a2, uint32_t a3,
    uint32_t b0, uint32_t b1)
{
    asm volatile(
        "mma.sync.aligned.m16n8k16.row.col.f32.f16.f16.f32 "
        "{%0,%1,%2,%3}, {%4,%5,%6,%7}, {%8,%9}, {%0,%1,%2,%3};"
        : "+f"(c[0]), "+f"(c[1]), "+f"(c[2]), "+f"(c[3])
        : "r"(a0), "r"(a1), "r"(a2), "r"(a3), "r"(b0), "r"(b1));
}

__device__ __forceinline__ float warpReduceSum(float v) {
#pragma unroll
    for (int o = 16; o > 0; o >>= 1) v += __shfl_xor_sync(0xffffffffu, v, o);
    return v;
}
__device__ __forceinline__ float blockReduceSum(float v) {
    __shared__ float sh[8];
    __shared__ float res;
    int lane = threadIdx.x & 31, w = threadIdx.x >> 5;
    v = warpReduceSum(v);
    if (lane == 0) sh[w] = v;
    __syncthreads();
    if (w == 0) {
        float t = (lane < 8) ? sh[lane] : 0.0f;
        t = warpReduceSum(t);
        if (lane == 0) res = t;
    }
    __syncthreads();
    float r = res;
    __syncthreads();
    return r;
}

// ---------------- convert x + 4 weights to fp16 (one launch) ---------------
#define NX4 ((int)(SY / 4))
#define NW4 (D_MODEL * D_MODEL / 4)
__global__ void __launch_bounds__(256)
convert_h(const float4* __restrict__ x,
          const float4* __restrict__ Wq, const float4* __restrict__ Wk,
          const float4* __restrict__ Wv, const float4* __restrict__ Wo,
          __half2* __restrict__ xh, __half2* __restrict__ wh)
{
    int n4 = NX4 + 4 * NW4;
    for (int i = blockIdx.x * blockDim.x + threadIdx.x; i < n4;
         i += gridDim.x * blockDim.x) {
        const float4* src;
        __half2* dst;
        if (i < NX4) { src = x + i; dst = xh + 2 * (long long)i; }
        else {
            int j = i - NX4;
            int ws = j / NW4, off = j - ws * NW4;
            src = (ws == 0 ? Wq : ws == 1 ? Wk : ws == 2 ? Wv : Wo) + off;
            dst = wh + 2 * ((long long)ws * NW4 + off);
        }
        float4 v = *src;
        dst[0] = __floats2half2_rn(v.x, v.y);
        dst[1] = __floats2half2_rn(v.z, v.w);
    }
}

// ---------------- fp16 GEMM NT core (projections) --------------------------
// C[128 x 128 tile] = A[M,K] * B[N,K]^T. A,B fp16 row-major. f32 accum.
#define PSTRH 40
template<bool OUTH>
__device__ __forceinline__ void gemm_nt_h(
    const __half* __restrict__ A, int lda,
    const __half* __restrict__ B, int ldb,
    void* __restrict__ Cv, int ldc, int K)
{
    __shared__ __half As[2][128 * PSTRH];
    __shared__ __half Bs[2][128 * PSTRH];

    int t    = threadIdx.x;
    int w    = t >> 5, lane = t & 31;
    int wm   = w >> 2, wn = w & 3;
    int g    = lane >> 2, tg = lane & 3;

    const __half* Ag = A + (long long)(blockIdx.y * 128) * lda;
    const __half* Bg = B + (long long)(blockIdx.x * 128) * ldb;

    int lr = t >> 1;             // 0..127: row
    int lc = (t & 1) * 16;       // 0 or 16

    float acc[4][4][4];
#pragma unroll
    for (int i = 0; i < 4; i++)
#pragma unroll
        for (int j = 0; j < 4; j++)
#pragma unroll
            for (int q = 0; q < 4; q++) acc[i][j][q] = 0.0f;

    auto load_tile = [&](int kt, int s) {
        long long ko = (long long)kt * 32;
        cp16(&As[s][lr * PSTRH + lc],     Ag + (long long)lr * lda + ko + lc);
        cp16(&As[s][lr * PSTRH + lc + 8], Ag + (long long)lr * lda + ko + lc + 8);
        cp16(&Bs[s][lr * PSTRH + lc],     Bg + (long long)lr * ldb + ko + lc);
        cp16(&Bs[s][lr * PSTRH + lc + 8], Bg + (long long)lr * ldb + ko + lc + 8);
    };

    int KT = K / 32;
    load_tile(0, 0);
    CP_COMMIT();

    for (int kt = 0; kt < KT; kt++) {
        if (kt + 1 < KT) load_tile(kt + 1, (kt + 1) & 1);
        CP_COMMIT();
        CP_WAIT(1);
        __syncthreads();

        const __half* as = As[kt & 1];
        const __half* bs = Bs[kt & 1];

#pragma unroll
        for (int kh = 0; kh < 2; kh++) {
            int kk = kh * 16;
            uint32_t af[4][4];
#pragma unroll
            for (int i = 0; i < 4; i++) {
                int r = wm * 64 + i * 16 + g;
                af[i][0] = *(const uint32_t*)&as[r * PSTRH + kk + 2 * tg];
                af[i][1] = *(const uint32_t*)&as[(r + 8) * PSTRH + kk + 2 * tg];
                af[i][2] = *(const uint32_t*)&as[r * PSTRH + kk + 8 + 2 * tg];
                af[i][3] = *(const uint32_t*)&as[(r + 8) * PSTRH + kk + 8 + 2 * tg];
            }
            uint32_t bf[4][2];
#pragma unroll
            for (int j = 0; j < 4; j++) {
                int n = wn * 32 + j * 8 + g;
                bf[j][0] = *(const uint32_t*)&bs[n * PSTRH + kk + 2 * tg];
                bf[j][1] = *(const uint32_t*)&bs[n * PSTRH + kk + 8 + 2 * tg];
            }
#pragma unroll
            for (int i = 0; i < 4; i++)
#pragma unroll
                for (int j = 0; j < 4; j++)
                    mma_f16(acc[i][j], af[i][0], af[i][1], af[i][2], af[i][3],
                            bf[j][0], bf[j][1]);
        }
        __syncthreads();
    }

#pragma unroll
    for (int i = 0; i < 4; i++) {
        long long r0 = blockIdx.y * 128 + wm * 64 + i * 16 + g;
#pragma unroll
        for (int j = 0; j < 4; j++) {
            int col = blockIdx.x * 128 + wn * 32 + j * 8 + tg * 2;
            if (OUTH) {
                __half* C = (__half*)Cv;
                *(__half2*)(C + r0 * ldc + col) =
                    __floats2half2_rn(acc[i][j][0], acc[i][j][1]);
                *(__half2*)(C + (r0 + 8) * ldc + col) =
                    __floats2half2_rn(acc[i][j][2], acc[i][j][3]);
            } else {
                float* C = (float*)Cv;
                *(float2*)(C + r0 * ldc + col) =
                    make_float2(acc[i][j][0], acc[i][j][1]);
                *(float2*)(C + (r0 + 8) * ldc + col) =
                    make_float2(acc[i][j][2], acc[i][j][3]);
            }
        }
    }
}

__global__ void __launch_bounds__(256)
qkv_proj_h(const __half* __restrict__ xh, const __half* __restrict__ wh,
           __half* __restrict__ q, __half* __restrict__ k, __half* __restrict__ v)
{
    const __half* B = wh + (long long)blockIdx.z * D_MODEL * D_MODEL;
    __half*       C = (blockIdx.z == 0) ? q : (blockIdx.z == 1) ? k : v;
    gemm_nt_h<true>(xh, D_MODEL, B, D_MODEL, C, D_MODEL, D_MODEL);
}

__global__ void __launch_bounds__(256)
out_proj_h(const __half* __restrict__ ch, const __half* __restrict__ wh,
           float* __restrict__ o)
{
    gemm_nt_h<false>(ch, D_MODEL, wh + 3LL * D_MODEL * D_MODEL,
                     D_MODEL, o, D_MODEL, D_MODEL);
}

// ---------------- fp16 scores: sc = half(exp(QK^T/8)), l += rowsum ---------
// Staged epilogue: exp values go through smem (aliasing the dead Q/K tiles)
// and stream out as coalesced 16B rows (fixes 50% sector waste of the old
// scattered half2 stores).
#define HS 72
#define SSTG 136
#define SC_SMEM (2 * 128 * HS * 2)     /* 36864 B; >= 128*SSTG*2 = 34816 */
__global__ void __launch_bounds__(256)
scores_exp_h(const __half* __restrict__ q, const __half* __restrict__ k,
             __half* __restrict__ sc, float* __restrict__ l)
{
    extern __shared__ char sraw[];
    __half* Qs    = (__half*)sraw;          // 128 x HS
    __half* Ksm   = Qs + 128 * HS;          // 128 x HS
    __half* stage = (__half*)sraw;          // aliases Qs/Ksm after MMA

    int z = blockIdx.z, zb = z >> 4, zh = z & 15;
    const long long SBH = (long long)SEQ * D_MODEL;
    const __half* qb = q + (long long)zb * SBH + zh * DK
                         + (long long)(blockIdx.y * 128) * D_MODEL;
    const __half* kb = k + (long long)zb * SBH + zh * DK
                         + (long long)(blockIdx.x * 128) * D_MODEL;

    int t = threadIdx.x, w = t >> 5, lane = t & 31;
    int wm = w >> 2, wn = w & 3;
    int g = lane >> 2, tg = lane & 3;

#pragma unroll
    for (int i = t; i < 1024; i += 256) {
        int r = i >> 3, c8 = (i & 7) * 8;
        cp16(&Qs[r * HS + c8],  qb + (long long)r * D_MODEL + c8);
        cp16(&Ksm[r * HS + c8], kb + (long long)r * D_MODEL + c8);
    }
    CP_COMMIT();
    CP_WAIT(0);
    __syncthreads();

    float c[4][4][4];
#pragma unroll
    for (int i = 0; i < 4; i++)
#pragma unroll
        for (int j = 0; j < 4; j++)
#pragma unroll
            for (int qq = 0; qq < 4; qq++) c[i][j][qq] = 0.0f;

#pragma unroll
    for (int ks = 0; ks < 4; ks++) {
        int k0 = ks * 16;
        uint32_t af[4][4];
#pragma unroll
        for (int i = 0; i < 4; i++) {
            int r = wm * 64 + i * 16 + g;
            af[i][0] = *(const uint32_t*)&Qs[r * HS + k0 + 2 * tg];
            af[i][1] = *(const uint32_t*)&Qs[(r + 8) * HS + k0 + 2 * tg];
            af[i][2] = *(const uint32_t*)&Qs[r * HS + k0 + 8 + 2 * tg];
            af[i][3] = *(const uint32_t*)&Qs[(r + 8) * HS + k0 + 8 + 2 * tg];
        }
#pragma unroll
        for (int j = 0; j < 4; j++) {
            int n = wn * 32 + j * 8 + g;
            uint32_t b0 = *(const uint32_t*)&Ksm[n * HS + k0 + 2 * tg];
            uint32_t b1 = *(const uint32_t*)&Ksm[n * HS + k0 + 8 + 2 * tg];
#pragma unroll
            for (int i = 0; i < 4; i++)
                mma_f16(c[i][j], af[i][0], af[i][1], af[i][2], af[i][3], b0, b1);
        }
    }
    __syncthreads();   // Qs/Ksm dead -> stage may overwrite

    // exp -> stage (smem) + row sums
    float* lb = l + (long long)z * SEQ + blockIdx.y * 128;
#pragma unroll
    for (int i = 0; i < 4; i++) {
        int rl = wm * 64 + i * 16 + g;
        float s0 = 0.0f, s1 = 0.0f;
#pragma unroll
        for (int j = 0; j < 4; j++) {
            float e0 = __expf(c[i][j][0] * 0.125f);
            float e1 = __expf(c[i][j][1] * 0.125f);
            float e2 = __expf(c[i][j][2] * 0.125f);
            float e3 = __expf(c[i][j][3] * 0.125f);
            int col = wn * 32 + j * 8 + 2 * tg;
            *(__half2*)&stage[rl * SSTG + col]       = __floats2half2_rn(e0, e1);
            *(__half2*)&stage[(rl + 8) * SSTG + col] = __floats2half2_rn(e2, e3);
            s0 += e0 + e1;
            s1 += e2 + e3;
        }
        s0 += __shfl_xor_sync(0xffffffffu, s0, 1);
        s0 += __shfl_xor_sync(0xffffffffu, s0, 2);
        s1 += __shfl_xor_sync(0xffffffffu, s1, 1);
        s1 += __shfl_xor_sync(0xffffffffu, s1, 2);
        if (tg == 0) {
            atomicAdd(&lb[rl],     s0);
            atomicAdd(&lb[rl + 8], s1);
        }
    }
    __syncthreads();

    // coalesced 16B streaming stores: 128 rows x 128 halves
    __half* cb = sc + (long long)z * SEQ * SEQ
                    + (long long)(blockIdx.y * 128) * SEQ + blockIdx.x * 128;
#pragma unroll
    for (int i = t; i < 2048; i += 256) {
        int r = i >> 4, c8 = (i & 15) * 8;
        __stcs((float4*)&cb[(long long)r * SEQ + c8],
               *(const float4*)&stage[r * SSTG + c8]);
    }
}

// ---------------- per-head V transpose (fp16): Vt[bh][d][s] ----------------
__global__ void __launch_bounds__(256)
transpose_v_h(const __half* __restrict__ v, __half* __restrict__ vt)
{
    __shared__ __half tile[32][34];
    int bh = blockIdx.z;
    int b = bh >> 4, h = bh & 15;
    int s0 = blockIdx.x * 32, d0 = blockIdx.y * 32;
    int tx = threadIdx.x, ty = threadIdx.y;

    const __half* src = v + (long long)b * SEQ * D_MODEL + h * DK;
#pragma unroll
    for (int i = ty; i < 32; i += 8)
        tile[i][tx] = src[(long long)(s0 + i) * D_MODEL + d0 + tx];
    __syncthreads();
    __half* dst = vt + (long long)bh * DK * SEQ;
#pragma unroll
    for (int i = ty; i < 32; i += 8)
        dst[(long long)(d0 + i) * SEQ + s0 + tx] = tile[tx][i];
}

// ---------------- fused: attn emit + ctx = expP @ V (fp16 MMA) -------------
#define FH 72
#define FC_SMEM ((2 * 128 * FH + 2 * 64 * FH) * 2 + 128 * 4)

__global__ void __launch_bounds__(256)
fused_ctx_h(const __half* __restrict__ expsc, const float* __restrict__ lsum,
            const __half* __restrict__ vt, float* __restrict__ attn,
            __half* __restrict__ ctx)
{
    extern __shared__ char smraw[];
    __half* As0 = (__half*)smraw;               // 128 x 72
    __half* As1 = As0 + 128 * FH;
    __half* Bs0 = As1 + 128 * FH;               // 64 x 72
    __half* Bs1 = Bs0 + 64 * FH;
    float* invl = (float*)(Bs1 + 64 * FH);      // 128

    int bh = blockIdx.y, b = bh >> 4, h = bh & 15;
    int q0 = blockIdx.x * 128;

    const __half* sc_b = expsc + ((long long)bh * SEQ + q0) * SEQ;
    const __half* vt_b = vt + (long long)bh * DK * SEQ;
    float* at_b = attn + ((long long)bh * SEQ + q0) * SEQ;

    int t = threadIdx.x, w = t >> 5, lane = t & 31;
    int wm = w >> 2, wn = w & 3;               // 2x4 warps: m64 x n16 tiles
    int g = lane >> 2, tg = lane & 3;

    auto loadChunk = [&](__half* Ad, __half* Bd, int k0) {
#pragma unroll
        for (int i = t; i < 1024; i += 256) {          // A: 128x64 halves
            int r = i >> 3, c8 = (i & 7) * 8;
            cp16(&Ad[r * FH + c8], sc_b + (long long)r * SEQ + k0 + c8);
        }
#pragma unroll
        for (int i = t; i < 512; i += 256) {           // B: 64x64 halves
            int r = i >> 3, c8 = (i & 7) * 8;
            cp16(&Bd[r * FH + c8], vt_b + (long long)r * SEQ + k0 + c8);
        }
    };

    if (t < 128) invl[t] = 1.0f / lsum[(long long)bh * SEQ + q0 + t];

    float acc[4][2][4];
#pragma unroll
    for (int i = 0; i < 4; i++)
#pragma unroll
        for (int j = 0; j < 2; j++)
#pragma unroll
            for (int qq = 0; qq < 4; qq++) acc[i][j][qq] = 0.0f;

    loadChunk(As0, Bs0, 0);
    CP_COMMIT();
    __syncthreads();   // invl visible

    for (int kt = 0; kt < SEQ / 64; kt++) {
        int k0 = kt * 64;
        __half* as = (kt & 1) ? As1 : As0;
        __half* bs = (kt & 1) ? Bs1 : Bs0;

        if (kt < SEQ / 64 - 1) {
            loadChunk((kt & 1) ? As0 : As1, (kt & 1) ? Bs0 : Bs1, k0 + 64);
            CP_COMMIT();
            CP_WAIT(1);
        } else {
            CP_WAIT(0);
        }
        __syncthreads();

        // attn emit first (stores in flight during MMA): p = expP * invl
#pragma unroll
        for (int i = t; i < 1024; i += 256) {
            int r = i >> 3, c8 = (i & 7) * 8;
            float iv = invl[r];
            const __half2* ph = (const __half2*)&as[r * FH + c8];
            float* po = at_b + (long long)r * SEQ + k0 + c8;
            float4 o0, o1;
            float2 x0 = __half22float2(ph[0]);
            float2 x1 = __half22float2(ph[1]);
            float2 x2 = __half22float2(ph[2]);
            float2 x3 = __half22float2(ph[3]);
            o0.x = x0.x * iv; o0.y = x0.y * iv; o0.z = x1.x * iv; o0.w = x1.y * iv;
            o1.x = x2.x * iv; o1.y = x2.y * iv; o1.z = x3.x * iv; o1.w = x3.y * iv;
            __stcs((float4*)po, o0);
            __stcs((float4*)(po + 4), o1);
        }

        // ctx += expP @ Vt^T  (fp16 MMA, K=16 per step)
#pragma unroll
        for (int ks = 0; ks < 4; ks++) {
            int kk = ks * 16;
            uint32_t af[4][4];
#pragma unroll
            for (int i = 0; i < 4; i++) {
                int r = wm * 64 + i * 16 + g;
                af[i][0] = *(const uint32_t*)&as[r * FH + kk + 2 * tg];
                af[i][1] = *(const uint32_t*)&as[(r + 8) * FH + kk + 2 * tg];
                af[i][2] = *(const uint32_t*)&as[r * FH + kk + 8 + 2 * tg];
                af[i][3] = *(const uint32_t*)&as[(r + 8) * FH + kk + 8 + 2 * tg];
            }
#pragma unroll
            for (int j = 0; j < 2; j++) {
                int n = wn * 16 + j * 8 + g;
                uint32_t b0 = *(const uint32_t*)&bs[n * FH + kk + 2 * tg];
                uint32_t b1 = *(const uint32_t*)&bs[n * FH + kk + 8 + 2 * tg];
#pragma unroll
                for (int i = 0; i < 4; i++)
                    mma_f16(acc[i][j], af[i][0], af[i][1], af[i][2], af[i][3],
                            b0, b1);
            }
        }
        __syncthreads();   // before next iteration reuses buffers
    }

    // ctx epilogue: scale by invl, emit fp16 (out_proj consumes fp16)
    __half* cb = ctx + ((long long)b * SEQ + q0) * D_MODEL + h * DK;
#pragma unroll
    for (int i = 0; i < 4; i++) {
        int r = wm * 64 + i * 16 + g;
        float iv0 = invl[r], iv1 = invl[r + 8];
#pragma unroll
        for (int j = 0; j < 2; j++) {
            int col = wn * 16 + j * 8 + tg * 2;
            *(__half2*)(cb + (long long)r * D_MODEL + col) =
                __floats2half2_rn(acc[i][j][0] * iv0, acc[i][j][1] * iv0);
            *(__half2*)(cb + (long long)(r + 8) * D_MODEL + col) =
                __floats2half2_rn(acc[i][j][2] * iv1, acc[i][j][3] * iv1);
        }
    }
}

// ---------------- bias + residual + LayerNorm ------------------------------
__global__ void __launch_bounds__(256)
bias_res_ln(const float* __restrict__ o, const float* __restrict__ x,
            const float* __restrict__ bo, const float* __restrict__ gamma,
            const float* __restrict__ beta, float* __restrict__ y)
{
    long long row = blockIdx.x;
    int tid = threadIdx.x;
    const float4* o4 = (const float4*)(o + row * D_MODEL);
    const float4* x4 = (const float4*)(x + row * D_MODEL);
    const float4* b4 = (const float4*)bo;
    const float4* g4 = (const float4*)gamma;
    const float4* be4 = (const float4*)beta;

    float4 ov = o4[tid], xv = x4[tid], bv = b4[tid];
    float4 v;
    v.x = ov.x + xv.x + bv.x;
    v.y = ov.y + xv.y + bv.y;
    v.z = ov.z + xv.z + bv.z;
    v.w = ov.w + xv.w + bv.w;

    float s  = v.x + v.y + v.z + v.w;
    float sq = v.x * v.x + v.y * v.y + v.z * v.z + v.w * v.w;
    s  = blockReduceSum(s);
    sq = blockReduceSum(sq);

    float mean = s * (1.0f / D_MODEL);
    float var  = sq * (1.0f / D_MODEL) - mean * mean;
    float rstd = rsqrtf(var + LN_EPS);

    float4 gv = g4[tid], bev = be4[tid];
    float4 r;
    r.x = (v.x - mean) * rstd * gv.x + bev.x;
    r.y = (v.y - mean) * rstd * gv.y + bev.y;
    r.z = (v.z - mean) * rstd * gv.z + bev.z;
    r.w = (v.w - mean) * rstd * gv.w + bev.w;
    ((float4*)(y + row * D_MODEL))[tid] = r;
}

// ---------------- launch ---------------------------------------------------
extern "C" void kernel_launch(void* const* d_in, const int* in_sizes, int n_in,
                              void* d_out, int out_size)
{
    const float* x     = (const float*)d_in[0];
    const float* Wq    = (const float*)d_in[1];
    const float* Wk    = (const float*)d_in[2];
    const float* Wv    = (const float*)d_in[3];
    const float* Wo    = (const float*)d_in[4];
    const float* bo    = (const float*)d_in[5];
    const float* gamma = (const float*)d_in[6];
    const float* beta  = (const float*)d_in[7];

    float* y_out    = (float*)d_out;
    float* attn_out = nullptr;
    if ((long long)out_size >= SY + SA) {
        attn_out = y_out + SY;                 // outputs concatenated: y, attn
    } else if ((long long)out_size == SA) {
        attn_out = y_out;                      // attn-only output
        y_out = nullptr;
    }

    __half *q, *k, *v, *vt, *xh, *wh, *ch, *sch;
    float *ob, *scf, *lptr;
    cudaGetSymbolAddress((void**)&q,    g_q);
    cudaGetSymbolAddress((void**)&k,    g_k);
    cudaGetSymbolAddress((void**)&v,    g_v);
    cudaGetSymbolAddress((void**)&vt,   g_vt);
    cudaGetSymbolAddress((void**)&xh,   g_xh);
    cudaGetSymbolAddress((void**)&wh,   g_wh);
    cudaGetSymbolAddress((void**)&ch,   g_ch);
    cudaGetSymbolAddress((void**)&sch,  g_sch);
    cudaGetSymbolAddress((void**)&ob,   g_o);
    cudaGetSymbolAddress((void**)&scf,  g_sc);
    cudaGetSymbolAddress((void**)&lptr, g_l);

    float* attn = attn_out ? attn_out : scf;

    static int smem_set = 0;
    if (!smem_set) {
        cudaFuncSetAttribute(fused_ctx_h,
            cudaFuncAttributeMaxDynamicSharedMemorySize, FC_SMEM);
        cudaFuncSetAttribute(scores_exp_h,
            cudaFuncAttributeMaxDynamicSharedMemorySize, SC_SMEM);
        smem_set = 1;
    }

    cudaMemsetAsync(lptr, 0, (size_t)BH * SEQ * sizeof(float));

    // convert x + weights to fp16 (single launch)
    convert_h<<<2048, 256>>>((const float4*)x, (const float4*)Wq,
                             (const float4*)Wk, (const float4*)Wv,
                             (const float4*)Wo, (__half2*)xh, (__half2*)wh);

    // projections (fp16 MMA) -> fp16 q,k,v
    qkv_proj_h<<<dim3(8, 32, 3), 256>>>(xh, wh, q, k, v);

    // fp16 exp-scores (staged coalesced stores) + f32 row sums
    scores_exp_h<<<dim3(16, 16, BH), 256, SC_SMEM>>>(q, k, sch, lptr);

    // fp16 V^T per head
    transpose_v_h<<<dim3(SEQ / 32, DK / 32, BH), dim3(32, 8)>>>(v, vt);

    // attn emit + ctx GEMM (fp16 MMA, async pipelined) -> fp16 ctx
    fused_ctx_h<<<dim3(16, BH), 256, FC_SMEM>>>(sch, lptr, vt, attn, ch);

    if (y_out) {
        out_proj_h<<<dim3(8, 32), 256>>>(ch, wh, ob);
        bias_res_ln<<<ROWS, 256>>>(ob, x, bo, gamma, beta, y_out);
    }
}